// round 1
// baseline (speedup 1.0000x reference)
#include <cuda_runtime.h>
#include <math.h>

// Problem dims (fixed by the reference)
#define TT 2048   // tokens
#define EE 2048   // embed
#define HH 16     // heads
#define LL 512    // latent
#define DD 128    // head dim
#define RA_WIN 64

// ---------------- scratch (allocation-free: device globals) ----------------
__device__ float g_Q[TT * EE];                 // [T, H*D]    16 MB
__device__ float g_latk[TT * LL];              // [T, L]       4 MB
__device__ float g_latv[TT * LL];              // [T, L]       4 MB
__device__ float g_qlat[(size_t)HH * TT * LL]; // [H, T, L]   64 MB
__device__ float g_V[TT * HH * DD];            // [T, H*D]    16 MB
__device__ float g_S[(size_t)HH * TT * TT];    // [H, T, T]  256 MB
__device__ float g_ctx[TT * HH * DD];          // [T, H*D]    16 MB

// ---------------- generic tiled SGEMM ----------------
// C[M,N] = A[M,K] @ op(B),  op(B) = B^T (B is [N,K]) when TB, else B is [K,N].
// Batched over blockIdx.z with element strides sA/sB/sC.
template <bool TB>
__global__ __launch_bounds__(256)
void gemm_kernel(const float* __restrict__ A, int lda, long long sA,
                 const float* __restrict__ B, int ldb, long long sB,
                 float* __restrict__ C, int ldc, long long sC,
                 int K)
{
    constexpr int BM = 64, BN = 64, BK = 16;
    A += (long long)blockIdx.z * sA;
    B += (long long)blockIdx.z * sB;
    C += (long long)blockIdx.z * sC;

    const int m0 = blockIdx.y * BM;
    const int n0 = blockIdx.x * BN;

    __shared__ float As[BK][BM];
    __shared__ float Bs[BK][BN];

    const int tid = threadIdx.x;
    const int ty = tid >> 4;       // 0..15
    const int tx = tid & 15;       // 0..15

    float acc[4][4] = {};

    for (int k0 = 0; k0 < K; k0 += BK) {
        // load A tile (BM x BK = 1024 elems, 4 per thread)
        #pragma unroll
        for (int i = 0; i < 4; ++i) {
            int e = tid + i * 256;
            int m = e >> 4;        // /BK
            int k = e & 15;        // %BK
            As[k][m] = A[(size_t)(m0 + m) * lda + (k0 + k)];
        }
        // load B tile (BK x BN = 1024 elems)
        #pragma unroll
        for (int i = 0; i < 4; ++i) {
            int e = tid + i * 256;
            if (TB) {
                int n = e >> 4;    // /BK
                int k = e & 15;
                Bs[k][n] = B[(size_t)(n0 + n) * ldb + (k0 + k)];
            } else {
                int k = e >> 6;    // /BN
                int n = e & 63;
                Bs[k][n] = B[(size_t)(k0 + k) * ldb + (n0 + n)];
            }
        }
        __syncthreads();

        #pragma unroll
        for (int kk = 0; kk < BK; ++kk) {
            float4 a4 = *(const float4*)&As[kk][ty * 4];
            float4 b4 = *(const float4*)&Bs[kk][tx * 4];
            float av[4] = {a4.x, a4.y, a4.z, a4.w};
            float bv[4] = {b4.x, b4.y, b4.z, b4.w};
            #pragma unroll
            for (int i = 0; i < 4; ++i)
                #pragma unroll
                for (int j = 0; j < 4; ++j)
                    acc[i][j] = fmaf(av[i], bv[j], acc[i][j]);
        }
        __syncthreads();
    }

    #pragma unroll
    for (int i = 0; i < 4; ++i)
        #pragma unroll
        for (int j = 0; j < 4; ++j)
            C[(size_t)(m0 + ty * 4 + i) * ldc + (n0 + tx * 4 + j)] = acc[i][j];
}

// ---------------- masked softmax over S rows ----------------
// S[h][t][s]: scale by 1/sqrt(L), *1.5 in causal band (t-s < 64), causal mask,
// softmax in-place. One block per (t, h); T/256 = 8 logits cached per thread.
__global__ __launch_bounds__(256)
void softmax_kernel(float* __restrict__ S)
{
    const int t = blockIdx.x;
    const int h = blockIdx.y;
    float* row = S + ((size_t)h * TT + t) * TT;

    const float inv = 0.044194173824159216f; // 1/sqrt(512)
    const int tid = threadIdx.x;

    __shared__ float red[256];

    float vals[TT / 256];
    float lmax = -INFINITY;
    #pragma unroll
    for (int i = 0; i < TT / 256; ++i) {
        int s = tid + i * 256;
        float v = -INFINITY;
        if (s <= t) {
            v = row[s] * inv;
            if (t - s < RA_WIN) v *= 1.5f;
            lmax = fmaxf(lmax, v);
        }
        vals[i] = v;
    }
    red[tid] = lmax;
    __syncthreads();
    #pragma unroll
    for (int o = 128; o > 0; o >>= 1) {
        if (tid < o) red[tid] = fmaxf(red[tid], red[tid + o]);
        __syncthreads();
    }
    const float m = red[0];
    __syncthreads();

    float lsum = 0.f;
    #pragma unroll
    for (int i = 0; i < TT / 256; ++i) {
        int s = tid + i * 256;
        float e = 0.f;
        if (s <= t) {
            e = __expf(vals[i] - m);
            lsum += e;
        }
        vals[i] = e;
    }
    red[tid] = lsum;
    __syncthreads();
    #pragma unroll
    for (int o = 128; o > 0; o >>= 1) {
        if (tid < o) red[tid] += red[tid + o];
        __syncthreads();
    }
    const float inv_sum = 1.0f / red[0];

    #pragma unroll
    for (int i = 0; i < TT / 256; ++i) {
        int s = tid + i * 256;
        row[s] = vals[i] * inv_sum;  // zeros beyond t automatically (vals[i]=0)
    }
}

// ---------------- launch ----------------
extern "C" void kernel_launch(void* const* d_in, const int* in_sizes, int n_in,
                              void* d_out, int out_size)
{
    const float* hidden = (const float*)d_in[0]; // [T, E]
    const float* w_q    = (const float*)d_in[1]; // [E, E]
    const float* w_kd   = (const float*)d_in[2]; // [L, E]
    const float* w_vd   = (const float*)d_in[3]; // [L, E]
    const float* q2l    = (const float*)d_in[4]; // [H, D, L]
    const float* v_up   = (const float*)d_in[5]; // [H, L, D]
    const float* w_out  = (const float*)d_in[6]; // [E, E]
    float* out = (float*)d_out;                  // [T, E]

    float *Q, *latk, *latv, *qlat, *V, *S, *ctx;
    cudaGetSymbolAddress((void**)&Q,    g_Q);
    cudaGetSymbolAddress((void**)&latk, g_latk);
    cudaGetSymbolAddress((void**)&latv, g_latv);
    cudaGetSymbolAddress((void**)&qlat, g_qlat);
    cudaGetSymbolAddress((void**)&V,    g_V);
    cudaGetSymbolAddress((void**)&S,    g_S);
    cudaGetSymbolAddress((void**)&ctx,  g_ctx);

    dim3 blk(256);

    // 1) Q = hidden @ w_q^T                [2048,2048,2048]
    gemm_kernel<true><<<dim3(EE / 64, TT / 64, 1), blk>>>(
        hidden, EE, 0, w_q, EE, 0, Q, EE, 0, EE);

    // 2) latent_k = hidden @ w_k_down^T    [2048,512,2048]
    gemm_kernel<true><<<dim3(LL / 64, TT / 64, 1), blk>>>(
        hidden, EE, 0, w_kd, EE, 0, latk, LL, 0, EE);

    // 3) latent_v = hidden @ w_v_down^T
    gemm_kernel<true><<<dim3(LL / 64, TT / 64, 1), blk>>>(
        hidden, EE, 0, w_vd, EE, 0, latv, LL, 0, EE);

    // 4) q_latent[h] = Q[:, h*D:(h+1)*D] @ q2l[h]   (NN, batched over heads)
    gemm_kernel<false><<<dim3(LL / 64, TT / 64, HH), blk>>>(
        Q, EE, DD, q2l, LL, (long long)DD * LL,
        qlat, LL, (long long)TT * LL, DD);

    // 5) V[:, h] = latent_v @ v_up[h]               (NN, batched)
    gemm_kernel<false><<<dim3(DD / 64, TT / 64, HH), blk>>>(
        latv, LL, 0, v_up, DD, (long long)LL * DD,
        V, HH * DD, DD, LL);

    // 6) S[h] = q_latent[h] @ latent_k^T            (NT, batched)
    gemm_kernel<true><<<dim3(TT / 64, TT / 64, HH), blk>>>(
        qlat, LL, (long long)TT * LL, latk, LL, 0,
        S, TT, (long long)TT * TT, LL);

    // 7) masked softmax in-place on S
    softmax_kernel<<<dim3(TT, HH), blk>>>(S);

    // 8) ctx[:, h] = S[h] @ V[:, h]                 (NN, batched)
    gemm_kernel<false><<<dim3(DD / 64, TT / 64, HH), blk>>>(
        S, TT, (long long)TT * TT, V, HH * DD, DD,
        ctx, HH * DD, DD, TT);

    // 9) out = ctx @ w_out^T               [2048,2048,2048]
    gemm_kernel<true><<<dim3(EE / 64, TT / 64, 1), blk>>>(
        ctx, EE, 0, w_out, EE, 0, out, EE, 0, EE);
}

// round 3
// speedup vs baseline: 2.9383x; 2.9383x over previous
#include <cuda_runtime.h>
#include <cuda_bf16.h>
#include <math.h>
#include <stdint.h>

// Problem dims (fixed by the reference)
#define TT 2048   // tokens
#define EE 2048   // embed
#define HH 16     // heads
#define LL 512    // latent
#define DD 128    // head dim
#define RA_WIN 64

// ---------------- scratch (allocation-free: device globals) ----------------
__device__ float g_Q[TT * EE];
__device__ float g_latk[TT * LL];
__device__ float g_latv[TT * LL];
__device__ float g_qlat[(size_t)HH * TT * LL];
__device__ float g_V[TT * HH * DD];
__device__ float g_S[(size_t)HH * TT * TT];
__device__ float g_ctx[TT * HH * DD];

// ---------------- PTX wrappers ----------------
__device__ __forceinline__ void ldsm_x4(uint32_t& r0, uint32_t& r1,
                                        uint32_t& r2, uint32_t& r3,
                                        uint32_t addr) {
    asm volatile("ldmatrix.sync.aligned.m8n8.x4.shared.b16 {%0,%1,%2,%3}, [%4];\n"
                 : "=r"(r0), "=r"(r1), "=r"(r2), "=r"(r3)
                 : "r"(addr));
}

__device__ __forceinline__ void mma_bf16(float& c0, float& c1, float& c2, float& c3,
                                         uint32_t a0, uint32_t a1, uint32_t a2, uint32_t a3,
                                         uint32_t b0, uint32_t b1) {
    asm volatile("mma.sync.aligned.m16n8k16.row.col.f32.bf16.bf16.f32 "
                 "{%0,%1,%2,%3}, {%4,%5,%6,%7}, {%8,%9}, {%0,%1,%2,%3};\n"
                 : "+f"(c0), "+f"(c1), "+f"(c2), "+f"(c3)
                 : "r"(a0), "r"(a1), "r"(a2), "r"(a3), "r"(b0), "r"(b1));
}

__device__ __forceinline__ void split_bf16(float x, __nv_bfloat16& h, __nv_bfloat16& l) {
    h = __float2bfloat16(x);
    l = __float2bfloat16(x - __bfloat162float(h));
}

// ---------------- split-bf16 tensor-core GEMM ----------------
// C[M,N] = A[M,K] @ op(B); op(B)=B^T (B is [N,K]) if TB, else B is [K,N].
// Block tile 128x64, k-chunk 32, 4 warps (each 64x32).
template <bool TB>
__global__ __launch_bounds__(128)
void gemm_tc(const float* __restrict__ A, int lda, long long sA,
             const float* __restrict__ B, int ldb, long long sB,
             float* __restrict__ C, int ldc, long long sC,
             int K)
{
    constexpr int BK = 32;
    constexpr int LDS = BK + 8;   // padded row (bf16 elems)

    A += (long long)blockIdx.z * sA;
    B += (long long)blockIdx.z * sB;
    C += (long long)blockIdx.z * sC;

    const int m0 = blockIdx.y * 128;
    const int n0 = blockIdx.x * 64;

    __shared__ __nv_bfloat16 Ash[128][LDS];
    __shared__ __nv_bfloat16 Asl[128][LDS];
    __shared__ __nv_bfloat16 Bsh[64][LDS];
    __shared__ __nv_bfloat16 Bsl[64][LDS];

    const int tid = threadIdx.x;
    const int lane = tid & 31;
    const int wid = tid >> 5;
    const int wm = (wid >> 1) * 64;   // warp m offset in tile
    const int wn = (wid & 1) * 32;    // warp n offset in tile

    const uint32_t ash = (uint32_t)__cvta_generic_to_shared(&Ash[0][0]);
    const uint32_t asl = (uint32_t)__cvta_generic_to_shared(&Asl[0][0]);
    const uint32_t bsh = (uint32_t)__cvta_generic_to_shared(&Bsh[0][0]);
    const uint32_t bsl = (uint32_t)__cvta_generic_to_shared(&Bsl[0][0]);

    float acc[4][4][4] = {};

    for (int k0 = 0; k0 < K; k0 += BK) {
        // ---- load A tile [128 x 32] (row-major, k contiguous) ----
        {
            const int row0 = tid >> 3;       // 0..15
            const int c4 = (tid & 7) * 4;    // float4 col
            #pragma unroll
            for (int i = 0; i < 8; ++i) {
                int r = row0 + i * 16;
                float4 v = *(const float4*)&A[(size_t)(m0 + r) * lda + k0 + c4];
                __nv_bfloat16 h, l;
                split_bf16(v.x, h, l); Ash[r][c4 + 0] = h; Asl[r][c4 + 0] = l;
                split_bf16(v.y, h, l); Ash[r][c4 + 1] = h; Asl[r][c4 + 1] = l;
                split_bf16(v.z, h, l); Ash[r][c4 + 2] = h; Asl[r][c4 + 2] = l;
                split_bf16(v.w, h, l); Ash[r][c4 + 3] = h; Asl[r][c4 + 3] = l;
            }
        }
        // ---- load B tile into Bs[n][k] layout ----
        if (TB) {
            // B is [N,K]: rows n, k contiguous
            const int row0 = tid >> 3;
            const int c4 = (tid & 7) * 4;
            #pragma unroll
            for (int i = 0; i < 4; ++i) {
                int r = row0 + i * 16;
                float4 v = *(const float4*)&B[(size_t)(n0 + r) * ldb + k0 + c4];
                __nv_bfloat16 h, l;
                split_bf16(v.x, h, l); Bsh[r][c4 + 0] = h; Bsl[r][c4 + 0] = l;
                split_bf16(v.y, h, l); Bsh[r][c4 + 1] = h; Bsl[r][c4 + 1] = l;
                split_bf16(v.z, h, l); Bsh[r][c4 + 2] = h; Bsl[r][c4 + 2] = l;
                split_bf16(v.w, h, l); Bsh[r][c4 + 3] = h; Bsl[r][c4 + 3] = l;
            }
        } else {
            // B is [K,N]: rows k, n contiguous -> transpose into Bs[n][k]
            const int kr0 = tid >> 4;        // 0..7
            const int c4 = (tid & 15) * 4;   // n within 64
            #pragma unroll
            for (int i = 0; i < 4; ++i) {
                int k = kr0 + i * 8;
                float4 v = *(const float4*)&B[(size_t)(k0 + k) * ldb + n0 + c4];
                __nv_bfloat16 h, l;
                split_bf16(v.x, h, l); Bsh[c4 + 0][k] = h; Bsl[c4 + 0][k] = l;
                split_bf16(v.y, h, l); Bsh[c4 + 1][k] = h; Bsl[c4 + 1][k] = l;
                split_bf16(v.z, h, l); Bsh[c4 + 2][k] = h; Bsl[c4 + 2][k] = l;
                split_bf16(v.w, h, l); Bsh[c4 + 3][k] = h; Bsl[c4 + 3][k] = l;
            }
        }
        __syncthreads();

        // ---- two k16 steps ----
        #pragma unroll
        for (int kk = 0; kk < BK; kk += 16) {
            uint32_t Ah[4][4], Al[4][4], Bh[4][2], Bl[4][2];

            const uint32_t aoff =
                (uint32_t)(((wm + (lane & 15)) * LDS + kk + ((lane >> 4) << 3)) * 2);
            #pragma unroll
            for (int mi = 0; mi < 4; ++mi) {
                ldsm_x4(Ah[mi][0], Ah[mi][1], Ah[mi][2], Ah[mi][3],
                        ash + aoff + (uint32_t)(mi * 16 * LDS * 2));
                ldsm_x4(Al[mi][0], Al[mi][1], Al[mi][2], Al[mi][3],
                        asl + aoff + (uint32_t)(mi * 16 * LDS * 2));
            }
            const uint32_t boff =
                (uint32_t)(((wn + ((lane >> 4) << 3) + (lane & 7)) * LDS +
                            kk + (((lane >> 3) & 1) << 3)) * 2);
            #pragma unroll
            for (int nt = 0; nt < 2; ++nt) {
                ldsm_x4(Bh[2 * nt][0], Bh[2 * nt][1], Bh[2 * nt + 1][0], Bh[2 * nt + 1][1],
                        bsh + boff + (uint32_t)(nt * 16 * LDS * 2));
                ldsm_x4(Bl[2 * nt][0], Bl[2 * nt][1], Bl[2 * nt + 1][0], Bl[2 * nt + 1][1],
                        bsl + boff + (uint32_t)(nt * 16 * LDS * 2));
            }

            #pragma unroll
            for (int mi = 0; mi < 4; ++mi)
                #pragma unroll
                for (int ni = 0; ni < 4; ++ni)
                    mma_bf16(acc[mi][ni][0], acc[mi][ni][1], acc[mi][ni][2], acc[mi][ni][3],
                             Ah[mi][0], Ah[mi][1], Ah[mi][2], Ah[mi][3],
                             Bh[ni][0], Bh[ni][1]);
            #pragma unroll
            for (int mi = 0; mi < 4; ++mi)
                #pragma unroll
                for (int ni = 0; ni < 4; ++ni)
                    mma_bf16(acc[mi][ni][0], acc[mi][ni][1], acc[mi][ni][2], acc[mi][ni][3],
                             Ah[mi][0], Ah[mi][1], Ah[mi][2], Ah[mi][3],
                             Bl[ni][0], Bl[ni][1]);
            #pragma unroll
            for (int mi = 0; mi < 4; ++mi)
                #pragma unroll
                for (int ni = 0; ni < 4; ++ni)
                    mma_bf16(acc[mi][ni][0], acc[mi][ni][1], acc[mi][ni][2], acc[mi][ni][3],
                             Al[mi][0], Al[mi][1], Al[mi][2], Al[mi][3],
                             Bh[ni][0], Bh[ni][1]);
        }
        __syncthreads();
    }

    // ---- epilogue ----
    #pragma unroll
    for (int mi = 0; mi < 4; ++mi) {
        #pragma unroll
        for (int ni = 0; ni < 4; ++ni) {
            int r = m0 + wm + mi * 16 + (lane >> 2);
            int c = n0 + wn + ni * 8 + (lane & 3) * 2;
            *(float2*)&C[(size_t)r * ldc + c] =
                make_float2(acc[mi][ni][0], acc[mi][ni][1]);
            *(float2*)&C[(size_t)(r + 8) * ldc + c] =
                make_float2(acc[mi][ni][2], acc[mi][ni][3]);
        }
    }
}

// ---------------- masked softmax over S rows ----------------
__global__ __launch_bounds__(256)
void softmax_kernel(float* __restrict__ S)
{
    const int t = blockIdx.x;
    const int h = blockIdx.y;
    float* row = S + ((size_t)h * TT + t) * TT;

    const float inv = 0.044194173824159216f; // 1/sqrt(512)
    const int tid = threadIdx.x;

    __shared__ float red[256];

    float vals[TT / 256];
    float lmax = -INFINITY;
    #pragma unroll
    for (int i = 0; i < TT / 256; ++i) {
        int s = tid + i * 256;
        float v = -INFINITY;
        if (s <= t) {
            v = row[s] * inv;
            if (t - s < RA_WIN) v *= 1.5f;
            lmax = fmaxf(lmax, v);
        }
        vals[i] = v;
    }
    red[tid] = lmax;
    __syncthreads();
    #pragma unroll
    for (int o = 128; o > 0; o >>= 1) {
        if (tid < o) red[tid] = fmaxf(red[tid], red[tid + o]);
        __syncthreads();
    }
    const float m = red[0];
    __syncthreads();

    float lsum = 0.f;
    #pragma unroll
    for (int i = 0; i < TT / 256; ++i) {
        int s = tid + i * 256;
        float e = 0.f;
        if (s <= t) {
            e = __expf(vals[i] - m);
            lsum += e;
        }
        vals[i] = e;
    }
    red[tid] = lsum;
    __syncthreads();
    #pragma unroll
    for (int o = 128; o > 0; o >>= 1) {
        if (tid < o) red[tid] += red[tid + o];
        __syncthreads();
    }
    const float inv_sum = 1.0f / red[0];

    #pragma unroll
    for (int i = 0; i < TT / 256; ++i) {
        int s = tid + i * 256;
        row[s] = vals[i] * inv_sum;
    }
}

// ---------------- launch ----------------
extern "C" void kernel_launch(void* const* d_in, const int* in_sizes, int n_in,
                              void* d_out, int out_size)
{
    const float* hidden = (const float*)d_in[0]; // [T, E]
    const float* w_q    = (const float*)d_in[1]; // [E, E]
    const float* w_kd   = (const float*)d_in[2]; // [L, E]
    const float* w_vd   = (const float*)d_in[3]; // [L, E]
    const float* q2l    = (const float*)d_in[4]; // [H, D, L]
    const float* v_up   = (const float*)d_in[5]; // [H, L, D]
    const float* w_out  = (const float*)d_in[6]; // [E, E]
    float* out = (float*)d_out;                  // [T, E]

    float *Q, *latk, *latv, *qlat, *V, *S, *ctx;
    cudaGetSymbolAddress((void**)&Q,    g_Q);
    cudaGetSymbolAddress((void**)&latk, g_latk);
    cudaGetSymbolAddress((void**)&latv, g_latv);
    cudaGetSymbolAddress((void**)&qlat, g_qlat);
    cudaGetSymbolAddress((void**)&V,    g_V);
    cudaGetSymbolAddress((void**)&S,    g_S);
    cudaGetSymbolAddress((void**)&ctx,  g_ctx);

    dim3 blk(128);

    // 1) Q = hidden @ w_q^T                 [2048,2048,2048] NT
    gemm_tc<true><<<dim3(EE / 64, TT / 128, 1), blk>>>(
        hidden, EE, 0, w_q, EE, 0, Q, EE, 0, EE);

    // 2) latent_k = hidden @ w_k_down^T     [2048,512,2048] NT
    gemm_tc<true><<<dim3(LL / 64, TT / 128, 1), blk>>>(
        hidden, EE, 0, w_kd, EE, 0, latk, LL, 0, EE);

    // 3) latent_v = hidden @ w_v_down^T
    gemm_tc<true><<<dim3(LL / 64, TT / 128, 1), blk>>>(
        hidden, EE, 0, w_vd, EE, 0, latv, LL, 0, EE);

    // 4) q_latent[h] = Q[:, hD:(h+1)D] @ q2l[h]   [2048,512,128] NN batched
    gemm_tc<false><<<dim3(LL / 64, TT / 128, HH), blk>>>(
        Q, EE, DD, q2l, LL, (long long)DD * LL,
        qlat, LL, (long long)TT * LL, DD);

    // 5) V[:, h] = latent_v @ v_up[h]              [2048,128,512] NN batched
    gemm_tc<false><<<dim3(DD / 64, TT / 128, HH), blk>>>(
        latv, LL, 0, v_up, DD, (long long)LL * DD,
        V, HH * DD, DD, LL);

    // 6) S[h] = q_latent[h] @ latent_k^T           [2048,2048,512] NT batched
    gemm_tc<true><<<dim3(TT / 64, TT / 128, HH), blk>>>(
        qlat, LL, (long long)TT * LL, latk, LL, 0,
        S, TT, (long long)TT * TT, LL);

    // 7) masked softmax in-place on S
    softmax_kernel<<<dim3(TT, HH), dim3(256)>>>(S);

    // 8) ctx[:, h] = S[h] @ V[:, h]                [2048,128,2048] NN batched
    gemm_tc<false><<<dim3(DD / 64, TT / 128, HH), blk>>>(
        S, TT, (long long)TT * TT, V, HH * DD, DD,
        ctx, HH * DD, DD, TT);

    // 9) out = ctx @ w_out^T                [2048,2048,2048] NT
    gemm_tc<true><<<dim3(EE / 64, TT / 128, 1), blk>>>(
        ctx, EE, 0, w_out, EE, 0, out, EE, 0, EE);
}

// round 5
// speedup vs baseline: 4.0759x; 1.3871x over previous
#include <cuda_runtime.h>
#include <cuda_bf16.h>
#include <math.h>
#include <stdint.h>

// Problem dims (fixed by the reference)
#define TT 2048   // tokens
#define EE 2048   // embed
#define HH 16     // heads
#define LL 512    // latent
#define DD 128    // head dim
#define RA_WIN 64

typedef __nv_bfloat16 bf16;
typedef __nv_bfloat162 bf162;

// ---------------- scratch (allocation-free: device globals) ----------------
// split copies of inputs
__device__ bf16 g_hidh[TT * EE],  g_hidl[TT * EE];
__device__ bf16 g_wqh[EE * EE],   g_wql[EE * EE];
__device__ bf16 g_wkdh[LL * EE],  g_wkdl[LL * EE];
__device__ bf16 g_wvdh[LL * EE],  g_wvdl[LL * EE];
__device__ bf16 g_wouth[EE * EE], g_woutl[EE * EE];
__device__ bf16 g_q2lTh[HH * LL * DD], g_q2lTl[HH * LL * DD]; // [H][L][D]
__device__ bf16 g_vupTh[HH * DD * LL], g_vupTl[HH * DD * LL]; // [H][D][L]
// intermediates (hi/lo bf16)
__device__ bf16 g_Qh[TT * EE],   g_Ql[TT * EE];
__device__ bf16 g_latkh[TT * LL], g_latkl[TT * LL];
__device__ bf16 g_latvh[TT * LL], g_latvl[TT * LL];
__device__ bf16 g_qlath[(size_t)HH * TT * LL], g_qlatl[(size_t)HH * TT * LL];
__device__ bf16 g_Vh[TT * EE],   g_Vl[TT * EE];     // [T][H*D]
__device__ bf16 g_VTh[EE * TT],  g_VTl[EE * TT];    // [H*D][T]
__device__ bf16 g_Sh[(size_t)HH * TT * TT], g_Sl[(size_t)HH * TT * TT];
__device__ bf16 g_ctxh[TT * EE], g_ctxl[TT * EE];

// ---------------- helpers ----------------
__device__ __forceinline__ uint32_t smem_u32(const void* p) {
    uint32_t a;
    asm("{ .reg .u64 t; cvta.to.shared.u64 t, %1; cvt.u32.u64 %0, t; }"
        : "=r"(a) : "l"(p));
    return a;
}

__device__ __forceinline__ void cp16(uint32_t dst, const void* src) {
    asm volatile("cp.async.cg.shared.global [%0], [%1], 16;" :: "r"(dst), "l"(src));
}
__device__ __forceinline__ void cp_commit() {
    asm volatile("cp.async.commit_group;" ::: "memory");
}
template <int N>
__device__ __forceinline__ void cp_wait() {
    asm volatile("cp.async.wait_group %0;" :: "n"(N) : "memory");
}

__device__ __forceinline__ void ldsm_x4(uint32_t& r0, uint32_t& r1,
                                        uint32_t& r2, uint32_t& r3,
                                        uint32_t addr) {
    asm volatile("ldmatrix.sync.aligned.m8n8.x4.shared.b16 {%0,%1,%2,%3}, [%4];\n"
                 : "=r"(r0), "=r"(r1), "=r"(r2), "=r"(r3)
                 : "r"(addr));
}

__device__ __forceinline__ void mma_bf16(float& c0, float& c1, float& c2, float& c3,
                                         uint32_t a0, uint32_t a1, uint32_t a2, uint32_t a3,
                                         uint32_t b0, uint32_t b1) {
    asm volatile("mma.sync.aligned.m16n8k16.row.col.f32.bf16.bf16.f32 "
                 "{%0,%1,%2,%3}, {%4,%5,%6,%7}, {%8,%9}, {%0,%1,%2,%3};\n"
                 : "+f"(c0), "+f"(c1), "+f"(c2), "+f"(c3)
                 : "r"(a0), "r"(a1), "r"(a2), "r"(a3), "r"(b0), "r"(b1));
}

// ---------------- conversion kernels ----------------
__global__ __launch_bounds__(256)
void split_k(const float* __restrict__ in, bf16* __restrict__ h,
             bf16* __restrict__ l, int n4)
{
    int i = blockIdx.x * blockDim.x + threadIdx.x;
    if (i >= n4) return;
    float4 v = ((const float4*)in)[i];
    bf16 hx = __float2bfloat16(v.x), hy = __float2bfloat16(v.y);
    bf16 hz = __float2bfloat16(v.z), hw = __float2bfloat16(v.w);
    ((bf162*)h)[2 * i]     = bf162{hx, hy};
    ((bf162*)h)[2 * i + 1] = bf162{hz, hw};
    ((bf162*)l)[2 * i] = bf162{
        __float2bfloat16(v.x - __bfloat162float(hx)),
        __float2bfloat16(v.y - __bfloat162float(hy))};
    ((bf162*)l)[2 * i + 1] = bf162{
        __float2bfloat16(v.z - __bfloat162float(hz)),
        __float2bfloat16(v.w - __bfloat162float(hw))};
}

// in [z][R][C] fp32 -> out [z][C][R] hi/lo bf16 (tiled transpose)
__global__ __launch_bounds__(256)
void transposeSplit(const float* __restrict__ in, bf16* __restrict__ outh,
                    bf16* __restrict__ outl, int R, int C)
{
    __shared__ float t[32][33];
    const size_t zoff = (size_t)blockIdx.z * R * C;
    in += zoff; outh += zoff; outl += zoff;
    const int c0 = blockIdx.x * 32, r0 = blockIdx.y * 32;
    const int tx = threadIdx.x;
    for (int i = threadIdx.y; i < 32; i += 8)
        t[i][tx] = in[(size_t)(r0 + i) * C + c0 + tx];
    __syncthreads();
    for (int i = threadIdx.y; i < 32; i += 8) {
        float v = t[tx][i];
        bf16 hh = __float2bfloat16(v);
        outh[(size_t)(c0 + i) * R + r0 + tx] = hh;
        outl[(size_t)(c0 + i) * R + r0 + tx] =
            __float2bfloat16(v - __bfloat162float(hh));
    }
}

// bf16 pair transpose: in [R][C] -> out [C][R]
__global__ __launch_bounds__(256)
void transpose2(const bf16* __restrict__ inh, const bf16* __restrict__ inl,
                bf16* __restrict__ outh, bf16* __restrict__ outl, int R, int C)
{
    __shared__ bf16 th[32][33], tl[32][33];
    const int c0 = blockIdx.x * 32, r0 = blockIdx.y * 32;
    const int tx = threadIdx.x;
    for (int i = threadIdx.y; i < 32; i += 8) {
        th[i][tx] = inh[(size_t)(r0 + i) * C + c0 + tx];
        tl[i][tx] = inl[(size_t)(r0 + i) * C + c0 + tx];
    }
    __syncthreads();
    for (int i = threadIdx.y; i < 32; i += 8) {
        outh[(size_t)(c0 + i) * R + r0 + tx] = th[tx][i];
        outl[(size_t)(c0 + i) * R + r0 + tx] = tl[tx][i];
    }
}

// ---------------- split-bf16 NT GEMM (cp.async pipelined) ----------------
// C[M,N] = (Ah+Al)[M,K] @ (Bh+Bl)[N,K]^T, 3-pass (hh + hl + lh), fp32 acc.
// CTA 128x128, BK=32, 4 warps (64x64 each), 2-stage cp.async pipeline.
#define LDSP 40                    // padded row in bf16 elems (80B)
#define ROWB (LDSP * 2)            // 80
#define TILEB (128 * ROWB)         // 10240
#define STAGEB (4 * TILEB)         // 40960
#define OFF_AH 0
#define OFF_AL TILEB
#define OFF_BH (2 * TILEB)
#define OFF_BL (3 * TILEB)
#define GEMM_SMEM (2 * STAGEB)     // 81920

template <bool SPLIT_OUT>
__global__ __launch_bounds__(128, 2)
void gemm_ss(const bf16* __restrict__ Ah, const bf16* __restrict__ Al,
             int lda, long long sA,
             const bf16* __restrict__ Bh, const bf16* __restrict__ Bl,
             int ldb, long long sB,
             void* __restrict__ Cp0, void* __restrict__ Cp1,
             int ldc, long long sC, int K)
{
    extern __shared__ char smem[];
    const uint32_t sbase = smem_u32(smem);
    const int tid = threadIdx.x;
    const int lane = tid & 31;
    const int wid = tid >> 5;
    const int wm = (wid >> 1) * 64;
    const int wn = (wid & 1) * 64;

    Ah += (long long)blockIdx.z * sA;
    Al += (long long)blockIdx.z * sA;
    Bh += (long long)blockIdx.z * sB;
    Bl += (long long)blockIdx.z * sB;
    const int m0 = blockIdx.y * 128;
    const int n0 = blockIdx.x * 128;

    const int row = tid >> 2;      // 0..31 within 128? no: tid 0..127 -> row 0..31
    const int ch = tid & 3;

    // issue one stage of cp.async loads (A/B hi/lo tiles, 32 k-cols)
    auto issue = [&](int it, int buf) {
        const int k0 = it << 5;
        const uint32_t sb = sbase + buf * STAGEB;
        #pragma unroll
        for (int i = 0; i < 4; ++i) {
            int r = row + i * 32;
            uint32_t doff = (uint32_t)(r * ROWB + ch * 16);
            const bf16* sa = Ah + (size_t)(m0 + r) * lda + k0 + ch * 8;
            cp16(sb + OFF_AH + doff, sa);
            const bf16* sal = Al + (size_t)(m0 + r) * lda + k0 + ch * 8;
            cp16(sb + OFF_AL + doff, sal);
            const bf16* sbh = Bh + (size_t)(n0 + r) * ldb + k0 + ch * 8;
            cp16(sb + OFF_BH + doff, sbh);
            const bf16* sbl = Bl + (size_t)(n0 + r) * ldb + k0 + ch * 8;
            cp16(sb + OFF_BL + doff, sbl);
        }
        cp_commit();
    };

    float acc[4][8][4] = {};
    const int nIter = K >> 5;

    issue(0, 0);

    for (int it = 0; it < nIter; ++it) {
        const int buf = it & 1;
        if (it + 1 < nIter) {
            issue(it + 1, buf ^ 1);
            cp_wait<1>();
        } else {
            cp_wait<0>();
        }
        __syncthreads();

        const uint32_t sb = sbase + buf * STAGEB;
        #pragma unroll
        for (int kk = 0; kk < 32; kk += 16) {
            uint32_t Ahf[4][4], Alf[4][4], Bhf[8][2], Blf[8][2];

            const uint32_t abase =
                (uint32_t)(((wm + (lane & 15)) * LDSP + kk + ((lane >> 4) << 3)) * 2);
            #pragma unroll
            for (int mi = 0; mi < 4; ++mi) {
                ldsm_x4(Ahf[mi][0], Ahf[mi][1], Ahf[mi][2], Ahf[mi][3],
                        sb + OFF_AH + abase + (uint32_t)(mi * 16 * ROWB));
                ldsm_x4(Alf[mi][0], Alf[mi][1], Alf[mi][2], Alf[mi][3],
                        sb + OFF_AL + abase + (uint32_t)(mi * 16 * ROWB));
            }
            const uint32_t bbase =
                (uint32_t)(((wn + ((lane >> 4) << 3) + (lane & 7)) * LDSP +
                            kk + (((lane >> 3) & 1) << 3)) * 2);
            #pragma unroll
            for (int nt = 0; nt < 4; ++nt) {
                ldsm_x4(Bhf[2 * nt][0], Bhf[2 * nt][1],
                        Bhf[2 * nt + 1][0], Bhf[2 * nt + 1][1],
                        sb + OFF_BH + bbase + (uint32_t)(nt * 16 * ROWB));
                ldsm_x4(Blf[2 * nt][0], Blf[2 * nt][1],
                        Blf[2 * nt + 1][0], Blf[2 * nt + 1][1],
                        sb + OFF_BL + bbase + (uint32_t)(nt * 16 * ROWB));
            }

            #pragma unroll
            for (int mi = 0; mi < 4; ++mi)
                #pragma unroll
                for (int ni = 0; ni < 8; ++ni)
                    mma_bf16(acc[mi][ni][0], acc[mi][ni][1], acc[mi][ni][2], acc[mi][ni][3],
                             Ahf[mi][0], Ahf[mi][1], Ahf[mi][2], Ahf[mi][3],
                             Bhf[ni][0], Bhf[ni][1]);
            #pragma unroll
            for (int mi = 0; mi < 4; ++mi)
                #pragma unroll
                for (int ni = 0; ni < 8; ++ni)
                    mma_bf16(acc[mi][ni][0], acc[mi][ni][1], acc[mi][ni][2], acc[mi][ni][3],
                             Ahf[mi][0], Ahf[mi][1], Ahf[mi][2], Ahf[mi][3],
                             Blf[ni][0], Blf[ni][1]);
            #pragma unroll
            for (int mi = 0; mi < 4; ++mi)
                #pragma unroll
                for (int ni = 0; ni < 8; ++ni)
                    mma_bf16(acc[mi][ni][0], acc[mi][ni][1], acc[mi][ni][2], acc[mi][ni][3],
                             Alf[mi][0], Alf[mi][1], Alf[mi][2], Alf[mi][3],
                             Bhf[ni][0], Bhf[ni][1]);
        }
        __syncthreads();
    }

    // ---- epilogue ----
    if (SPLIT_OUT) {
        bf16* Ch = (bf16*)Cp0 + (long long)blockIdx.z * sC;
        bf16* Cl = (bf16*)Cp1 + (long long)blockIdx.z * sC;
        #pragma unroll
        for (int mi = 0; mi < 4; ++mi) {
            #pragma unroll
            for (int ni = 0; ni < 8; ++ni) {
                int r = m0 + wm + mi * 16 + (lane >> 2);
                int c = n0 + wn + ni * 8 + (lane & 3) * 2;
                #pragma unroll
                for (int half = 0; half < 2; ++half) {
                    float a0 = acc[mi][ni][2 * half], a1 = acc[mi][ni][2 * half + 1];
                    bf16 h0 = __float2bfloat16(a0), h1 = __float2bfloat16(a1);
                    size_t off = (size_t)(r + half * 8) * ldc + c;
                    *(bf162*)&Ch[off] = bf162{h0, h1};
                    *(bf162*)&Cl[off] = bf162{
                        __float2bfloat16(a0 - __bfloat162float(h0)),
                        __float2bfloat16(a1 - __bfloat162float(h1))};
                }
            }
        }
    } else {
        float* C = (float*)Cp0 + (long long)blockIdx.z * sC;
        #pragma unroll
        for (int mi = 0; mi < 4; ++mi) {
            #pragma unroll
            for (int ni = 0; ni < 8; ++ni) {
                int r = m0 + wm + mi * 16 + (lane >> 2);
                int c = n0 + wn + ni * 8 + (lane & 3) * 2;
                *(float2*)&C[(size_t)r * ldc + c] =
                    make_float2(acc[mi][ni][0], acc[mi][ni][1]);
                *(float2*)&C[(size_t)(r + 8) * ldc + c] =
                    make_float2(acc[mi][ni][2], acc[mi][ni][3]);
            }
        }
    }
}

// ---------------- masked softmax on hi/lo S ----------------
__global__ __launch_bounds__(256)
void softmax2(bf16* __restrict__ Sh, bf16* __restrict__ Sl)
{
    const int t = blockIdx.x;
    const int h = blockIdx.y;
    bf16* rowh = Sh + ((size_t)h * TT + t) * TT;
    bf16* rowl = Sl + ((size_t)h * TT + t) * TT;

    const float inv = 0.044194173824159216f; // 1/sqrt(512)
    const int tid = threadIdx.x;
    const int base = tid * 8;

    __shared__ float red[256];

    float vals[8];
    float lmax = -INFINITY;
    #pragma unroll
    for (int i = 0; i < 8; ++i) {
        int s = base + i;
        float v = -INFINITY;
        if (s <= t) {
            v = (__bfloat162float(rowh[s]) + __bfloat162float(rowl[s])) * inv;
            if (t - s < RA_WIN) v *= 1.5f;
            lmax = fmaxf(lmax, v);
        }
        vals[i] = v;
    }
    red[tid] = lmax;
    __syncthreads();
    #pragma unroll
    for (int o = 128; o > 0; o >>= 1) {
        if (tid < o) red[tid] = fmaxf(red[tid], red[tid + o]);
        __syncthreads();
    }
    const float m = red[0];
    __syncthreads();

    float lsum = 0.f;
    #pragma unroll
    for (int i = 0; i < 8; ++i) {
        int s = base + i;
        float e = 0.f;
        if (s <= t) { e = __expf(vals[i] - m); lsum += e; }
        vals[i] = e;
    }
    red[tid] = lsum;
    __syncthreads();
    #pragma unroll
    for (int o = 128; o > 0; o >>= 1) {
        if (tid < o) red[tid] += red[tid + o];
        __syncthreads();
    }
    const float inv_sum = 1.0f / red[0];

    #pragma unroll
    for (int i = 0; i < 8; ++i) {
        int s = base + i;
        float p = vals[i] * inv_sum;
        bf16 ph = __float2bfloat16(p);
        rowh[s] = ph;
        rowl[s] = __float2bfloat16(p - __bfloat162float(ph));
    }
}

// ---------------- launch ----------------
extern "C" void kernel_launch(void* const* d_in, const int* in_sizes, int n_in,
                              void* d_out, int out_size)
{
    const float* hidden = (const float*)d_in[0]; // [T, E]
    const float* w_q    = (const float*)d_in[1]; // [E, E]
    const float* w_kd   = (const float*)d_in[2]; // [L, E]
    const float* w_vd   = (const float*)d_in[3]; // [L, E]
    const float* q2l    = (const float*)d_in[4]; // [H, D, L]
    const float* v_up   = (const float*)d_in[5]; // [H, L, D]
    const float* w_out  = (const float*)d_in[6]; // [E, E]
    float* out = (float*)d_out;                  // [T, E]

    bf16 *hidh, *hidl, *wqh, *wql, *wkdh, *wkdl, *wvdh, *wvdl, *wouth, *woutl;
    bf16 *q2lTh, *q2lTl, *vupTh, *vupTl;
    bf16 *Qh, *Ql, *latkh, *latkl, *latvh, *latvl, *qlath, *qlatl;
    bf16 *Vh, *Vl, *VTh, *VTl, *Sh, *Sl, *ctxh, *ctxl;
    cudaGetSymbolAddress((void**)&hidh, g_hidh);   cudaGetSymbolAddress((void**)&hidl, g_hidl);
    cudaGetSymbolAddress((void**)&wqh, g_wqh);     cudaGetSymbolAddress((void**)&wql, g_wql);
    cudaGetSymbolAddress((void**)&wkdh, g_wkdh);   cudaGetSymbolAddress((void**)&wkdl, g_wkdl);
    cudaGetSymbolAddress((void**)&wvdh, g_wvdh);   cudaGetSymbolAddress((void**)&wvdl, g_wvdl);
    cudaGetSymbolAddress((void**)&wouth, g_wouth); cudaGetSymbolAddress((void**)&woutl, g_woutl);
    cudaGetSymbolAddress((void**)&q2lTh, g_q2lTh); cudaGetSymbolAddress((void**)&q2lTl, g_q2lTl);
    cudaGetSymbolAddress((void**)&vupTh, g_vupTh); cudaGetSymbolAddress((void**)&vupTl, g_vupTl);
    cudaGetSymbolAddress((void**)&Qh, g_Qh);       cudaGetSymbolAddress((void**)&Ql, g_Ql);
    cudaGetSymbolAddress((void**)&latkh, g_latkh); cudaGetSymbolAddress((void**)&latkl, g_latkl);
    cudaGetSymbolAddress((void**)&latvh, g_latvh); cudaGetSymbolAddress((void**)&latvl, g_latvl);
    cudaGetSymbolAddress((void**)&qlath, g_qlath); cudaGetSymbolAddress((void**)&qlatl, g_qlatl);
    cudaGetSymbolAddress((void**)&Vh, g_Vh);       cudaGetSymbolAddress((void**)&Vl, g_Vl);
    cudaGetSymbolAddress((void**)&VTh, g_VTh);     cudaGetSymbolAddress((void**)&VTl, g_VTl);
    cudaGetSymbolAddress((void**)&Sh, g_Sh);       cudaGetSymbolAddress((void**)&Sl, g_Sl);
    cudaGetSymbolAddress((void**)&ctxh, g_ctxh);   cudaGetSymbolAddress((void**)&ctxl, g_ctxl);

    cudaFuncSetAttribute(gemm_ss<true>,
                         cudaFuncAttributeMaxDynamicSharedMemorySize, GEMM_SMEM);
    cudaFuncSetAttribute(gemm_ss<false>,
                         cudaFuncAttributeMaxDynamicSharedMemorySize, GEMM_SMEM);

    // ---- conversions ----
    split_k<<<(TT * EE / 4 + 255) / 256, 256>>>(hidden, hidh, hidl, TT * EE / 4);
    split_k<<<(EE * EE / 4 + 255) / 256, 256>>>(w_q, wqh, wql, EE * EE / 4);
    split_k<<<(LL * EE / 4 + 255) / 256, 256>>>(w_kd, wkdh, wkdl, LL * EE / 4);
    split_k<<<(LL * EE / 4 + 255) / 256, 256>>>(w_vd, wvdh, wvdl, LL * EE / 4);
    split_k<<<(EE * EE / 4 + 255) / 256, 256>>>(w_out, wouth, woutl, EE * EE / 4);
    // q2l [H][D][L] -> [H][L][D]
    transposeSplit<<<dim3(LL / 32, DD / 32, HH), dim3(32, 8)>>>(q2l, q2lTh, q2lTl, DD, LL);
    // v_up [H][L][D] -> [H][D][L]
    transposeSplit<<<dim3(DD / 32, LL / 32, HH), dim3(32, 8)>>>(v_up, vupTh, vupTl, LL, DD);

    dim3 blk(128);
    const size_t sm = GEMM_SMEM;

    // 1) Q = hidden @ w_q^T  [2048,2048,2048]
    gemm_ss<true><<<dim3(EE / 128, TT / 128, 1), blk, sm>>>(
        hidh, hidl, EE, 0, wqh, wql, EE, 0, Qh, Ql, EE, 0, EE);

    // 2) latent_k = hidden @ w_k_down^T  [2048,512,2048]
    gemm_ss<true><<<dim3(LL / 128, TT / 128, 1), blk, sm>>>(
        hidh, hidl, EE, 0, wkdh, wkdl, EE, 0, latkh, latkl, LL, 0, EE);

    // 3) latent_v = hidden @ w_v_down^T
    gemm_ss<true><<<dim3(LL / 128, TT / 128, 1), blk, sm>>>(
        hidh, hidl, EE, 0, wvdh, wvdl, EE, 0, latvh, latvl, LL, 0, EE);

    // 4) q_latent[h] = Q[:,hD:] @ q2lT[h]^T  [2048,512,128]
    gemm_ss<true><<<dim3(LL / 128, TT / 128, HH), blk, sm>>>(
        Qh, Ql, EE, DD, q2lTh, q2lTl, DD, (long long)LL * DD,
        qlath, qlatl, LL, (long long)TT * LL, DD);

    // 5) V[:,h] = latent_v @ vupT[h]^T  [2048,128,512]
    gemm_ss<true><<<dim3(DD / 128, TT / 128, HH), blk, sm>>>(
        latvh, latvl, LL, 0, vupTh, vupTl, LL, (long long)DD * LL,
        Vh, Vl, EE, DD, LL);

    // 6) S[h] = q_latent[h] @ latent_k^T  [2048,2048,512]
    gemm_ss<true><<<dim3(TT / 128, TT / 128, HH), blk, sm>>>(
        qlath, qlatl, LL, (long long)TT * LL, latkh, latkl, LL, 0,
        Sh, Sl, TT, (long long)TT * TT, LL);

    // 7) V^T: [T][E] -> [E][T]
    transpose2<<<dim3(EE / 32, TT / 32), dim3(32, 8)>>>(Vh, Vl, VTh, VTl, TT, EE);

    // 8) masked softmax in-place on (Sh, Sl)
    softmax2<<<dim3(TT, HH), dim3(256)>>>(Sh, Sl);

    // 9) ctx[:,h] = attn[h] @ VT[h]^T  [2048,128,2048]
    gemm_ss<true><<<dim3(DD / 128, TT / 128, HH), blk, sm>>>(
        Sh, Sl, TT, (long long)TT * TT, VTh, VTl, TT, (long long)DD * TT,
        ctxh, ctxl, EE, DD, TT);

    // 10) out = ctx @ w_out^T  [2048,2048,2048] (fp32 out)
    gemm_ss<false><<<dim3(EE / 128, TT / 128, 1), blk, sm>>>(
        ctxh, ctxl, EE, 0, wouth, woutl, EE, 0, out, nullptr, EE, 0, EE);
}

// round 6
// speedup vs baseline: 5.6877x; 1.3954x over previous
#include <cuda_runtime.h>
#include <cuda_bf16.h>
#include <math.h>
#include <stdint.h>

// Problem dims (fixed by the reference)
#define TT 2048   // tokens
#define EE 2048   // embed
#define HH 16     // heads
#define LL 512    // latent
#define DD 128    // head dim
#define RA_WIN 64

typedef __nv_bfloat16 bf16;
typedef __nv_bfloat162 bf162;

// ---------------- scratch (allocation-free: device globals) ----------------
__device__ bf16 g_hidh[TT * EE],  g_hidl[TT * EE];
__device__ bf16 g_wqh[EE * EE],   g_wql[EE * EE];
__device__ bf16 g_wkdh[LL * EE],  g_wkdl[LL * EE];
__device__ bf16 g_wvdh[LL * EE],  g_wvdl[LL * EE];
__device__ bf16 g_wouth[EE * EE], g_woutl[EE * EE];
__device__ bf16 g_q2lTh[HH * LL * DD], g_q2lTl[HH * LL * DD]; // [H][L][D]
__device__ bf16 g_vupTh[HH * DD * LL], g_vupTl[HH * DD * LL]; // [H][D][L]
__device__ bf16 g_Qh[TT * EE],   g_Ql[TT * EE];
__device__ bf16 g_latkh[TT * LL], g_latkl[TT * LL];
__device__ bf16 g_latvh[TT * LL], g_latvl[TT * LL];
__device__ bf16 g_qlath[(size_t)HH * TT * LL], g_qlatl[(size_t)HH * TT * LL];
__device__ bf16 g_Vh[TT * EE],   g_Vl[TT * EE];     // [T][H*D]
__device__ bf16 g_VTh[EE * TT],  g_VTl[EE * TT];    // [H*D][T]
__device__ bf16 g_Sh[(size_t)HH * TT * TT], g_Sl[(size_t)HH * TT * TT];
__device__ bf16 g_ctxh[TT * EE], g_ctxl[TT * EE];

// ---------------- helpers ----------------
__device__ __forceinline__ uint32_t smem_u32(const void* p) {
    uint32_t a;
    asm("{ .reg .u64 t; cvta.to.shared.u64 t, %1; cvt.u32.u64 %0, t; }"
        : "=r"(a) : "l"(p));
    return a;
}

__device__ __forceinline__ void cp16(uint32_t dst, const void* src) {
    asm volatile("cp.async.cg.shared.global [%0], [%1], 16;" :: "r"(dst), "l"(src));
}
__device__ __forceinline__ void cp_commit() {
    asm volatile("cp.async.commit_group;" ::: "memory");
}
template <int N>
__device__ __forceinline__ void cp_wait() {
    asm volatile("cp.async.wait_group %0;" :: "n"(N) : "memory");
}

__device__ __forceinline__ void ldsm_x4(uint32_t& r0, uint32_t& r1,
                                        uint32_t& r2, uint32_t& r3,
                                        uint32_t addr) {
    asm volatile("ldmatrix.sync.aligned.m8n8.x4.shared.b16 {%0,%1,%2,%3}, [%4];\n"
                 : "=r"(r0), "=r"(r1), "=r"(r2), "=r"(r3)
                 : "r"(addr));
}

__device__ __forceinline__ void mma_bf16(float& c0, float& c1, float& c2, float& c3,
                                         uint32_t a0, uint32_t a1, uint32_t a2, uint32_t a3,
                                         uint32_t b0, uint32_t b1) {
    asm volatile("mma.sync.aligned.m16n8k16.row.col.f32.bf16.bf16.f32 "
                 "{%0,%1,%2,%3}, {%4,%5,%6,%7}, {%8,%9}, {%0,%1,%2,%3};\n"
                 : "+f"(c0), "+f"(c1), "+f"(c2), "+f"(c3)
                 : "r"(a0), "r"(a1), "r"(a2), "r"(a3), "r"(b0), "r"(b1));
}

// ---------------- conversion kernels ----------------
__global__ __launch_bounds__(256)
void split_k(const float* __restrict__ in, bf16* __restrict__ h,
             bf16* __restrict__ l, int n4)
{
    int i = blockIdx.x * blockDim.x + threadIdx.x;
    if (i >= n4) return;
    float4 v = ((const float4*)in)[i];
    bf16 hx = __float2bfloat16(v.x), hy = __float2bfloat16(v.y);
    bf16 hz = __float2bfloat16(v.z), hw = __float2bfloat16(v.w);
    ((bf162*)h)[2 * i]     = bf162{hx, hy};
    ((bf162*)h)[2 * i + 1] = bf162{hz, hw};
    ((bf162*)l)[2 * i] = bf162{
        __float2bfloat16(v.x - __bfloat162float(hx)),
        __float2bfloat16(v.y - __bfloat162float(hy))};
    ((bf162*)l)[2 * i + 1] = bf162{
        __float2bfloat16(v.z - __bfloat162float(hz)),
        __float2bfloat16(v.w - __bfloat162float(hw))};
}

// in [z][R][C] fp32 -> out [z][C][R] hi/lo bf16 (tiled transpose)
__global__ __launch_bounds__(256)
void transposeSplit(const float* __restrict__ in, bf16* __restrict__ outh,
                    bf16* __restrict__ outl, int R, int C)
{
    __shared__ float t[32][33];
    const size_t zoff = (size_t)blockIdx.z * R * C;
    in += zoff; outh += zoff; outl += zoff;
    const int c0 = blockIdx.x * 32, r0 = blockIdx.y * 32;
    const int tx = threadIdx.x;
    for (int i = threadIdx.y; i < 32; i += 8)
        t[i][tx] = in[(size_t)(r0 + i) * C + c0 + tx];
    __syncthreads();
    for (int i = threadIdx.y; i < 32; i += 8) {
        float v = t[tx][i];
        bf16 hh = __float2bfloat16(v);
        outh[(size_t)(c0 + i) * R + r0 + tx] = hh;
        outl[(size_t)(c0 + i) * R + r0 + tx] =
            __float2bfloat16(v - __bfloat162float(hh));
    }
}

// bf16 pair transpose: in [R][C] -> out [C][R]
__global__ __launch_bounds__(256)
void transpose2(const bf16* __restrict__ inh, const bf16* __restrict__ inl,
                bf16* __restrict__ outh, bf16* __restrict__ outl, int R, int C)
{
    __shared__ bf16 th[32][33], tl[32][33];
    const int c0 = blockIdx.x * 32, r0 = blockIdx.y * 32;
    const int tx = threadIdx.x;
    for (int i = threadIdx.y; i < 32; i += 8) {
        th[i][tx] = inh[(size_t)(r0 + i) * C + c0 + tx];
        tl[i][tx] = inl[(size_t)(r0 + i) * C + c0 + tx];
    }
    __syncthreads();
    for (int i = threadIdx.y; i < 32; i += 8) {
        outh[(size_t)(c0 + i) * R + r0 + tx] = th[tx][i];
        outl[(size_t)(c0 + i) * R + r0 + tx] = tl[tx][i];
    }
}

// ---------------- split-bf16 NT GEMM (cp.async pipelined) ----------------
// C[M,N] = (Ah+Al)[M,K] @ (Bh+Bl)[N,K]^T, 3-pass (hh + hl + lh), fp32 acc.
// CTA 128x128, BK=32, 4 warps (64x64 each), 2-stage cp.async pipeline.
// mode: 0 = plain, 1 = causal tile skip (skip n0 > m0+127), 2 = K-cap at
//       (blockIdx.y+1)*128 (attn rows only attend to s < m0+128).
#define LDSP 40                    // padded row in bf16 elems (80B)
#define ROWB (LDSP * 2)            // 80
#define TILEB (128 * ROWB)         // 10240
#define STAGEB (4 * TILEB)         // 40960
#define OFF_AH 0
#define OFF_AL TILEB
#define OFF_BH (2 * TILEB)
#define OFF_BL (3 * TILEB)
#define GEMM_SMEM (2 * STAGEB)     // 81920

template <bool SPLIT_OUT>
__global__ __launch_bounds__(128, 2)
void gemm_ss(const bf16* __restrict__ Ah, const bf16* __restrict__ Al,
             int lda, long long sA,
             const bf16* __restrict__ Bh, const bf16* __restrict__ Bl,
             int ldb, long long sB,
             void* __restrict__ Cp0, void* __restrict__ Cp1,
             int ldc, long long sC, int K, int mode)
{
    if (mode == 1 && blockIdx.x > blockIdx.y) return;

    extern __shared__ char smem[];
    const uint32_t sbase = smem_u32(smem);
    const int tid = threadIdx.x;
    const int lane = tid & 31;
    const int wid = tid >> 5;
    const int wm = (wid >> 1) * 64;
    const int wn = (wid & 1) * 64;

    Ah += (long long)blockIdx.z * sA;
    Al += (long long)blockIdx.z * sA;
    Bh += (long long)blockIdx.z * sB;
    Bl += (long long)blockIdx.z * sB;
    const int m0 = blockIdx.y * 128;
    const int n0 = blockIdx.x * 128;

    const int row = tid >> 2;
    const int ch = tid & 3;

    auto issue = [&](int it, int buf) {
        const int k0 = it << 5;
        const uint32_t sb = sbase + buf * STAGEB;
        #pragma unroll
        for (int i = 0; i < 4; ++i) {
            int r = row + i * 32;
            uint32_t doff = (uint32_t)(r * ROWB + ch * 16);
            cp16(sb + OFF_AH + doff, Ah + (size_t)(m0 + r) * lda + k0 + ch * 8);
            cp16(sb + OFF_AL + doff, Al + (size_t)(m0 + r) * lda + k0 + ch * 8);
            cp16(sb + OFF_BH + doff, Bh + (size_t)(n0 + r) * ldb + k0 + ch * 8);
            cp16(sb + OFF_BL + doff, Bl + (size_t)(n0 + r) * ldb + k0 + ch * 8);
        }
        cp_commit();
    };

    float acc[4][8][4] = {};
    int nIter = K >> 5;
    if (mode == 2) {
        int kc = (int)(blockIdx.y + 1) << 7;   // (y+1)*128
        if (kc < K) nIter = kc >> 5;
    }

    issue(0, 0);

    for (int it = 0; it < nIter; ++it) {
        const int buf = it & 1;
        if (it + 1 < nIter) {
            issue(it + 1, buf ^ 1);
            cp_wait<1>();
        } else {
            cp_wait<0>();
        }
        __syncthreads();

        const uint32_t sb = sbase + buf * STAGEB;
        #pragma unroll
        for (int kk = 0; kk < 32; kk += 16) {
            uint32_t Ahf[4][4], Alf[4][4], Bhf[8][2], Blf[8][2];

            const uint32_t abase =
                (uint32_t)(((wm + (lane & 15)) * LDSP + kk + ((lane >> 4) << 3)) * 2);
            #pragma unroll
            for (int mi = 0; mi < 4; ++mi) {
                ldsm_x4(Ahf[mi][0], Ahf[mi][1], Ahf[mi][2], Ahf[mi][3],
                        sb + OFF_AH + abase + (uint32_t)(mi * 16 * ROWB));
                ldsm_x4(Alf[mi][0], Alf[mi][1], Alf[mi][2], Alf[mi][3],
                        sb + OFF_AL + abase + (uint32_t)(mi * 16 * ROWB));
            }
            const uint32_t bbase =
                (uint32_t)(((wn + ((lane >> 4) << 3) + (lane & 7)) * LDSP +
                            kk + (((lane >> 3) & 1) << 3)) * 2);
            #pragma unroll
            for (int nt = 0; nt < 4; ++nt) {
                ldsm_x4(Bhf[2 * nt][0], Bhf[2 * nt][1],
                        Bhf[2 * nt + 1][0], Bhf[2 * nt + 1][1],
                        sb + OFF_BH + bbase + (uint32_t)(nt * 16 * ROWB));
                ldsm_x4(Blf[2 * nt][0], Blf[2 * nt][1],
                        Blf[2 * nt + 1][0], Blf[2 * nt + 1][1],
                        sb + OFF_BL + bbase + (uint32_t)(nt * 16 * ROWB));
            }

            #pragma unroll
            for (int mi = 0; mi < 4; ++mi)
                #pragma unroll
                for (int ni = 0; ni < 8; ++ni)
                    mma_bf16(acc[mi][ni][0], acc[mi][ni][1], acc[mi][ni][2], acc[mi][ni][3],
                             Ahf[mi][0], Ahf[mi][1], Ahf[mi][2], Ahf[mi][3],
                             Bhf[ni][0], Bhf[ni][1]);
            #pragma unroll
            for (int mi = 0; mi < 4; ++mi)
                #pragma unroll
                for (int ni = 0; ni < 8; ++ni)
                    mma_bf16(acc[mi][ni][0], acc[mi][ni][1], acc[mi][ni][2], acc[mi][ni][3],
                             Ahf[mi][0], Ahf[mi][1], Ahf[mi][2], Ahf[mi][3],
                             Blf[ni][0], Blf[ni][1]);
            #pragma unroll
            for (int mi = 0; mi < 4; ++mi)
                #pragma unroll
                for (int ni = 0; ni < 8; ++ni)
                    mma_bf16(acc[mi][ni][0], acc[mi][ni][1], acc[mi][ni][2], acc[mi][ni][3],
                             Alf[mi][0], Alf[mi][1], Alf[mi][2], Alf[mi][3],
                             Bhf[ni][0], Bhf[ni][1]);
        }
        __syncthreads();
    }

    // ---- epilogue ----
    if (SPLIT_OUT) {
        bf16* Ch = (bf16*)Cp0 + (long long)blockIdx.z * sC;
        bf16* Cl = (bf16*)Cp1 + (long long)blockIdx.z * sC;
        #pragma unroll
        for (int mi = 0; mi < 4; ++mi) {
            #pragma unroll
            for (int ni = 0; ni < 8; ++ni) {
                int r = m0 + wm + mi * 16 + (lane >> 2);
                int c = n0 + wn + ni * 8 + (lane & 3) * 2;
                #pragma unroll
                for (int half = 0; half < 2; ++half) {
                    float a0 = acc[mi][ni][2 * half], a1 = acc[mi][ni][2 * half + 1];
                    bf16 h0 = __float2bfloat16(a0), h1 = __float2bfloat16(a1);
                    size_t off = (size_t)(r + half * 8) * ldc + c;
                    *(bf162*)&Ch[off] = bf162{h0, h1};
                    *(bf162*)&Cl[off] = bf162{
                        __float2bfloat16(a0 - __bfloat162float(h0)),
                        __float2bfloat16(a1 - __bfloat162float(h1))};
                }
            }
        }
    } else {
        float* C = (float*)Cp0 + (long long)blockIdx.z * sC;
        #pragma unroll
        for (int mi = 0; mi < 4; ++mi) {
            #pragma unroll
            for (int ni = 0; ni < 8; ++ni) {
                int r = m0 + wm + mi * 16 + (lane >> 2);
                int c = n0 + wn + ni * 8 + (lane & 3) * 2;
                *(float2*)&C[(size_t)r * ldc + c] =
                    make_float2(acc[mi][ni][0], acc[mi][ni][1]);
                *(float2*)&C[(size_t)(r + 8) * ldc + c] =
                    make_float2(acc[mi][ni][2], acc[mi][ni][3]);
            }
        }
    }
}

// ---------------- masked softmax on hi/lo S (causal-bounded) ----------------
// Processes only s < bound = ceil128(t+1); writes exact zeros for t < s < bound
// (the attn*V GEMM's K-cap never reads beyond bound).
__global__ __launch_bounds__(256)
void softmax2(bf16* __restrict__ Sh, bf16* __restrict__ Sl)
{
    const int t = blockIdx.x;
    const int h = blockIdx.y;
    bf16* rowh = Sh + ((size_t)h * TT + t) * TT;
    bf16* rowl = Sl + ((size_t)h * TT + t) * TT;

    const float inv = 0.044194173824159216f; // 1/sqrt(512)
    const int tid = threadIdx.x;
    const int bound = ((t >> 7) + 1) << 7;

    __shared__ float red[256];

    float vals[8];
    float lmax = -INFINITY;
    #pragma unroll
    for (int i = 0; i < 8; ++i) {
        int s = tid + i * 256;
        if (s >= bound) break;
        float v = -INFINITY;
        if (s <= t) {
            v = (__bfloat162float(rowh[s]) + __bfloat162float(rowl[s])) * inv;
            if (t - s < RA_WIN) v *= 1.5f;
            lmax = fmaxf(lmax, v);
        }
        vals[i] = v;
    }
    red[tid] = lmax;
    __syncthreads();
    #pragma unroll
    for (int o = 128; o > 0; o >>= 1) {
        if (tid < o) red[tid] = fmaxf(red[tid], red[tid + o]);
        __syncthreads();
    }
    const float m = red[0];
    __syncthreads();

    float lsum = 0.f;
    #pragma unroll
    for (int i = 0; i < 8; ++i) {
        int s = tid + i * 256;
        if (s >= bound) break;
        float e = 0.f;
        if (s <= t) { e = __expf(vals[i] - m); lsum += e; }
        vals[i] = e;
    }
    red[tid] = lsum;
    __syncthreads();
    #pragma unroll
    for (int o = 128; o > 0; o >>= 1) {
        if (tid < o) red[tid] += red[tid + o];
        __syncthreads();
    }
    const float inv_sum = 1.0f / red[0];

    #pragma unroll
    for (int i = 0; i < 8; ++i) {
        int s = tid + i * 256;
        if (s >= bound) break;
        float p = vals[i] * inv_sum;
        bf16 ph = __float2bfloat16(p);
        rowh[s] = ph;
        rowl[s] = __float2bfloat16(p - __bfloat162float(ph));
    }
}

// ---------------- launch ----------------
extern "C" void kernel_launch(void* const* d_in, const int* in_sizes, int n_in,
                              void* d_out, int out_size)
{
    const float* hidden = (const float*)d_in[0]; // [T, E]
    const float* w_q    = (const float*)d_in[1]; // [E, E]
    const float* w_kd   = (const float*)d_in[2]; // [L, E]
    const float* w_vd   = (const float*)d_in[3]; // [L, E]
    const float* q2l    = (const float*)d_in[4]; // [H, D, L]
    const float* v_up   = (const float*)d_in[5]; // [H, L, D]
    const float* w_out  = (const float*)d_in[6]; // [E, E]
    float* out = (float*)d_out;                  // [T, E]

    bf16 *hidh, *hidl, *wqh, *wql, *wkdh, *wkdl, *wvdh, *wvdl, *wouth, *woutl;
    bf16 *q2lTh, *q2lTl, *vupTh, *vupTl;
    bf16 *Qh, *Ql, *latkh, *latkl, *latvh, *latvl, *qlath, *qlatl;
    bf16 *Vh, *Vl, *VTh, *VTl, *Sh, *Sl, *ctxh, *ctxl;
    cudaGetSymbolAddress((void**)&hidh, g_hidh);   cudaGetSymbolAddress((void**)&hidl, g_hidl);
    cudaGetSymbolAddress((void**)&wqh, g_wqh);     cudaGetSymbolAddress((void**)&wql, g_wql);
    cudaGetSymbolAddress((void**)&wkdh, g_wkdh);   cudaGetSymbolAddress((void**)&wkdl, g_wkdl);
    cudaGetSymbolAddress((void**)&wvdh, g_wvdh);   cudaGetSymbolAddress((void**)&wvdl, g_wvdl);
    cudaGetSymbolAddress((void**)&wouth, g_wouth); cudaGetSymbolAddress((void**)&woutl, g_woutl);
    cudaGetSymbolAddress((void**)&q2lTh, g_q2lTh); cudaGetSymbolAddress((void**)&q2lTl, g_q2lTl);
    cudaGetSymbolAddress((void**)&vupTh, g_vupTh); cudaGetSymbolAddress((void**)&vupTl, g_vupTl);
    cudaGetSymbolAddress((void**)&Qh, g_Qh);       cudaGetSymbolAddress((void**)&Ql, g_Ql);
    cudaGetSymbolAddress((void**)&latkh, g_latkh); cudaGetSymbolAddress((void**)&latkl, g_latkl);
    cudaGetSymbolAddress((void**)&latvh, g_latvh); cudaGetSymbolAddress((void**)&latvl, g_latvl);
    cudaGetSymbolAddress((void**)&qlath, g_qlath); cudaGetSymbolAddress((void**)&qlatl, g_qlatl);
    cudaGetSymbolAddress((void**)&Vh, g_Vh);       cudaGetSymbolAddress((void**)&Vl, g_Vl);
    cudaGetSymbolAddress((void**)&VTh, g_VTh);     cudaGetSymbolAddress((void**)&VTl, g_VTl);
    cudaGetSymbolAddress((void**)&Sh, g_Sh);       cudaGetSymbolAddress((void**)&Sl, g_Sl);
    cudaGetSymbolAddress((void**)&ctxh, g_ctxh);   cudaGetSymbolAddress((void**)&ctxl, g_ctxl);

    cudaFuncSetAttribute(gemm_ss<true>,
                         cudaFuncAttributeMaxDynamicSharedMemorySize, GEMM_SMEM);
    cudaFuncSetAttribute(gemm_ss<false>,
                         cudaFuncAttributeMaxDynamicSharedMemorySize, GEMM_SMEM);

    // ---- conversions ----
    split_k<<<(TT * EE / 4 + 255) / 256, 256>>>(hidden, hidh, hidl, TT * EE / 4);
    split_k<<<(EE * EE / 4 + 255) / 256, 256>>>(w_q, wqh, wql, EE * EE / 4);
    split_k<<<(LL * EE / 4 + 255) / 256, 256>>>(w_kd, wkdh, wkdl, LL * EE / 4);
    split_k<<<(LL * EE / 4 + 255) / 256, 256>>>(w_vd, wvdh, wvdl, LL * EE / 4);
    split_k<<<(EE * EE / 4 + 255) / 256, 256>>>(w_out, wouth, woutl, EE * EE / 4);
    transposeSplit<<<dim3(LL / 32, DD / 32, HH), dim3(32, 8)>>>(q2l, q2lTh, q2lTl, DD, LL);
    transposeSplit<<<dim3(DD / 32, LL / 32, HH), dim3(32, 8)>>>(v_up, vupTh, vupTl, LL, DD);

    dim3 blk(128);
    const size_t sm = GEMM_SMEM;

    // 1) Q = hidden @ w_q^T  [2048,2048,2048]
    gemm_ss<true><<<dim3(EE / 128, TT / 128, 1), blk, sm>>>(
        hidh, hidl, EE, 0, wqh, wql, EE, 0, Qh, Ql, EE, 0, EE, 0);

    // 2) latent_k = hidden @ w_k_down^T  [2048,512,2048]
    gemm_ss<true><<<dim3(LL / 128, TT / 128, 1), blk, sm>>>(
        hidh, hidl, EE, 0, wkdh, wkdl, EE, 0, latkh, latkl, LL, 0, EE, 0);

    // 3) latent_v = hidden @ w_v_down^T
    gemm_ss<true><<<dim3(LL / 128, TT / 128, 1), blk, sm>>>(
        hidh, hidl, EE, 0, wvdh, wvdl, EE, 0, latvh, latvl, LL, 0, EE, 0);

    // 4) q_latent[h] = Q[:,hD:] @ q2lT[h]^T  [2048,512,128]
    gemm_ss<true><<<dim3(LL / 128, TT / 128, HH), blk, sm>>>(
        Qh, Ql, EE, DD, q2lTh, q2lTl, DD, (long long)LL * DD,
        qlath, qlatl, LL, (long long)TT * LL, DD, 0);

    // 5) V[:,h] = latent_v @ vupT[h]^T  [2048,128,512]
    gemm_ss<true><<<dim3(DD / 128, TT / 128, HH), blk, sm>>>(
        latvh, latvl, LL, 0, vupTh, vupTl, LL, (long long)DD * LL,
        Vh, Vl, EE, DD, LL, 0);

    // 6) S[h] = q_latent[h] @ latent_k^T  [2048,2048,512] — causal tile skip
    gemm_ss<true><<<dim3(TT / 128, TT / 128, HH), blk, sm>>>(
        qlath, qlatl, LL, (long long)TT * LL, latkh, latkl, LL, 0,
        Sh, Sl, TT, (long long)TT * TT, LL, 1);

    // 7) V^T: [T][E] -> [E][T]
    transpose2<<<dim3(EE / 32, TT / 32), dim3(32, 8)>>>(Vh, Vl, VTh, VTl, TT, EE);

    // 8) masked softmax in-place on (Sh, Sl), causal-bounded
    softmax2<<<dim3(TT, HH), dim3(256)>>>(Sh, Sl);

    // 9) ctx[:,h] = attn[h] @ VT[h]^T  [2048,128,2048] — K capped per row tile
    gemm_ss<true><<<dim3(DD / 128, TT / 128, HH), blk, sm>>>(
        Sh, Sl, TT, (long long)TT * TT, VTh, VTl, TT, (long long)DD * TT,
        ctxh, ctxl, EE, DD, TT, 2);

    // 10) out = ctx @ w_out^T  [2048,2048,2048] (fp32 out)
    gemm_ss<false><<<dim3(EE / 128, TT / 128, 1), blk, sm>>>(
        ctxh, ctxl, EE, 0, wouth, woutl, EE, 0, out, nullptr, EE, 0, EE, 0);
}

// round 7
// speedup vs baseline: 6.6880x; 1.1759x over previous
#include <cuda_runtime.h>
#include <cuda_fp16.h>
#include <math.h>
#include <stdint.h>

// Problem dims (fixed by the reference)
#define TT 2048   // tokens
#define EE 2048   // embed
#define HH 16     // heads
#define LL 512    // latent
#define DD 128    // head dim
#define RA_WIN 64

typedef __half f16;
typedef __half2 f162;

// ---------------- scratch (allocation-free: device globals) ----------------
__device__ f16 g_hidh[TT * EE],  g_hidl[TT * EE];
__device__ f16 g_wqh[EE * EE],   g_wql[EE * EE];
__device__ f16 g_wkdh[LL * EE],  g_wkdl[LL * EE];
__device__ f16 g_wvdh[LL * EE],  g_wvdl[LL * EE];
__device__ f16 g_wouth[EE * EE], g_woutl[EE * EE];
__device__ f16 g_q2lTh[HH * LL * DD], g_q2lTl[HH * LL * DD]; // [H][L][D]
__device__ f16 g_vupTh[HH * DD * LL], g_vupTl[HH * DD * LL]; // [H][D][L]
__device__ f16 g_Qh[TT * EE],   g_Ql[TT * EE];
__device__ f16 g_latkh[TT * LL], g_latkl[TT * LL];
__device__ f16 g_latvh[TT * LL], g_latvl[TT * LL];
__device__ f16 g_qlath[(size_t)HH * TT * LL], g_qlatl[(size_t)HH * TT * LL];
__device__ f16 g_Vh[TT * EE],   g_Vl[TT * EE];     // [T][H*D]
__device__ f16 g_VTh[EE * TT],  g_VTl[EE * TT];    // [H*D][T]
__device__ f16 g_Sh[(size_t)HH * TT * TT], g_Sl[(size_t)HH * TT * TT];
__device__ f16 g_ctxh[TT * EE], g_ctxl[TT * EE];

// ---------------- helpers ----------------
__device__ __forceinline__ uint32_t smem_u32(const void* p) {
    uint32_t a;
    asm("{ .reg .u64 t; cvta.to.shared.u64 t, %1; cvt.u32.u64 %0, t; }"
        : "=r"(a) : "l"(p));
    return a;
}

__device__ __forceinline__ void cp16(uint32_t dst, const void* src) {
    asm volatile("cp.async.cg.shared.global [%0], [%1], 16;" :: "r"(dst), "l"(src));
}
__device__ __forceinline__ void cp_commit() {
    asm volatile("cp.async.commit_group;" ::: "memory");
}
template <int N>
__device__ __forceinline__ void cp_wait() {
    asm volatile("cp.async.wait_group %0;" :: "n"(N) : "memory");
}

__device__ __forceinline__ void ldsm_x4(uint32_t& r0, uint32_t& r1,
                                        uint32_t& r2, uint32_t& r3,
                                        uint32_t addr) {
    asm volatile("ldmatrix.sync.aligned.m8n8.x4.shared.b16 {%0,%1,%2,%3}, [%4];\n"
                 : "=r"(r0), "=r"(r1), "=r"(r2), "=r"(r3)
                 : "r"(addr));
}

__device__ __forceinline__ void mma_f16(float& c0, float& c1, float& c2, float& c3,
                                        uint32_t a0, uint32_t a1, uint32_t a2, uint32_t a3,
                                        uint32_t b0, uint32_t b1) {
    asm volatile("mma.sync.aligned.m16n8k16.row.col.f32.f16.f16.f32 "
                 "{%0,%1,%2,%3}, {%4,%5,%6,%7}, {%8,%9}, {%0,%1,%2,%3};\n"
                 : "+f"(c0), "+f"(c1), "+f"(c2), "+f"(c3)
                 : "r"(a0), "r"(a1), "r"(a2), "r"(a3), "r"(b0), "r"(b1));
}

// ---------------- conversion kernels ----------------
__global__ __launch_bounds__(256)
void split_k(const float* __restrict__ in, f16* __restrict__ h,
             f16* __restrict__ l, int n4)
{
    int i = blockIdx.x * blockDim.x + threadIdx.x;
    if (i >= n4) return;
    float4 v = ((const float4*)in)[i];
    f16 hx = __float2half(v.x), hy = __float2half(v.y);
    f16 hz = __float2half(v.z), hw = __float2half(v.w);
    ((f162*)h)[2 * i]     = __halves2half2(hx, hy);
    ((f162*)h)[2 * i + 1] = __halves2half2(hz, hw);
    ((f162*)l)[2 * i] = __halves2half2(
        __float2half(v.x - __half2float(hx)),
        __float2half(v.y - __half2float(hy)));
    ((f162*)l)[2 * i + 1] = __halves2half2(
        __float2half(v.z - __half2float(hz)),
        __float2half(v.w - __half2float(hw)));
}

// in [z][R][C] fp32 -> out [z][C][R] hi/lo f16 (tiled transpose)
__global__ __launch_bounds__(256)
void transposeSplit(const float* __restrict__ in, f16* __restrict__ outh,
                    f16* __restrict__ outl, int R, int C)
{
    __shared__ float t[32][33];
    const size_t zoff = (size_t)blockIdx.z * R * C;
    in += zoff; outh += zoff; outl += zoff;
    const int c0 = blockIdx.x * 32, r0 = blockIdx.y * 32;
    const int tx = threadIdx.x;
    for (int i = threadIdx.y; i < 32; i += 8)
        t[i][tx] = in[(size_t)(r0 + i) * C + c0 + tx];
    __syncthreads();
    for (int i = threadIdx.y; i < 32; i += 8) {
        float v = t[tx][i];
        f16 hh = __float2half(v);
        outh[(size_t)(c0 + i) * R + r0 + tx] = hh;
        outl[(size_t)(c0 + i) * R + r0 + tx] =
            __float2half(v - __half2float(hh));
    }
}

// f16 pair transpose: in [R][C] -> out [C][R]
__global__ __launch_bounds__(256)
void transpose2(const f16* __restrict__ inh, const f16* __restrict__ inl,
                f16* __restrict__ outh, f16* __restrict__ outl, int R, int C)
{
    __shared__ f16 th[32][33], tl[32][33];
    const int c0 = blockIdx.x * 32, r0 = blockIdx.y * 32;
    const int tx = threadIdx.x;
    for (int i = threadIdx.y; i < 32; i += 8) {
        th[i][tx] = inh[(size_t)(r0 + i) * C + c0 + tx];
        tl[i][tx] = inl[(size_t)(r0 + i) * C + c0 + tx];
    }
    __syncthreads();
    for (int i = threadIdx.y; i < 32; i += 8) {
        outh[(size_t)(c0 + i) * R + r0 + tx] = th[tx][i];
        outl[(size_t)(c0 + i) * R + r0 + tx] = tl[tx][i];
    }
}

// ---------------- split-fp16 NT GEMM (cp.async pipelined) ----------------
// C[M,N] = (Ah+Al)[M,K] @ op(B)^T, fp32 acc.
// NPASS=3: B=(Bh+Bl), passes AhBh + AhBl + AlBh (error ~2^-22)
// NPASS=2: B=Bh only, passes AhBh + AlBh (error ~2^-12, skips Bl entirely)
// CTA 128x128, BK=32, 4 warps (64x64 each), 2-stage cp.async pipeline.
// mode: 0 = plain, 1 = causal tile skip (skip n0 > m0+127), 2 = K-cap at
//       (blockIdx.y+1)*128 (attn rows only attend to s < m0+128).
#define LDSP 40                    // padded row in f16 elems (80B)
#define ROWB (LDSP * 2)            // 80
#define TILEB (128 * ROWB)         // 10240
#define STAGEB (4 * TILEB)         // 40960
#define OFF_AH 0
#define OFF_AL TILEB
#define OFF_BH (2 * TILEB)
#define OFF_BL (3 * TILEB)
#define GEMM_SMEM (2 * STAGEB)     // 81920

template <bool SPLIT_OUT, int NPASS>
__global__ __launch_bounds__(128, 2)
void gemm_ss(const f16* __restrict__ Ah, const f16* __restrict__ Al,
             int lda, long long sA,
             const f16* __restrict__ Bh, const f16* __restrict__ Bl,
             int ldb, long long sB,
             void* __restrict__ Cp0, void* __restrict__ Cp1,
             int ldc, long long sC, int K, int mode)
{
    if (mode == 1 && blockIdx.x > blockIdx.y) return;

    extern __shared__ char smem[];
    const uint32_t sbase = smem_u32(smem);
    const int tid = threadIdx.x;
    const int lane = tid & 31;
    const int wid = tid >> 5;
    const int wm = (wid >> 1) * 64;
    const int wn = (wid & 1) * 64;

    Ah += (long long)blockIdx.z * sA;
    Al += (long long)blockIdx.z * sA;
    Bh += (long long)blockIdx.z * sB;
    if (NPASS == 3) Bl += (long long)blockIdx.z * sB;
    const int m0 = blockIdx.y * 128;
    const int n0 = blockIdx.x * 128;

    const int row = tid >> 2;
    const int ch = tid & 3;

    auto issue = [&](int it, int buf) {
        const int k0 = it << 5;
        const uint32_t sb = sbase + buf * STAGEB;
        #pragma unroll
        for (int i = 0; i < 4; ++i) {
            int r = row + i * 32;
            uint32_t doff = (uint32_t)(r * ROWB + ch * 16);
            cp16(sb + OFF_AH + doff, Ah + (size_t)(m0 + r) * lda + k0 + ch * 8);
            cp16(sb + OFF_AL + doff, Al + (size_t)(m0 + r) * lda + k0 + ch * 8);
            cp16(sb + OFF_BH + doff, Bh + (size_t)(n0 + r) * ldb + k0 + ch * 8);
            if (NPASS == 3)
                cp16(sb + OFF_BL + doff, Bl + (size_t)(n0 + r) * ldb + k0 + ch * 8);
        }
        cp_commit();
    };

    float acc[4][8][4] = {};
    int nIter = K >> 5;
    if (mode == 2) {
        int kc = (int)(blockIdx.y + 1) << 7;   // (y+1)*128
        if (kc < K) nIter = kc >> 5;
    }

    issue(0, 0);

    for (int it = 0; it < nIter; ++it) {
        const int buf = it & 1;
        if (it + 1 < nIter) {
            issue(it + 1, buf ^ 1);
            cp_wait<1>();
        } else {
            cp_wait<0>();
        }
        __syncthreads();

        const uint32_t sb = sbase + buf * STAGEB;
        #pragma unroll
        for (int kk = 0; kk < 32; kk += 16) {
            uint32_t Ahf[4][4], Alf[4][4], Bhf[8][2], Blf[8][2];

            const uint32_t abase =
                (uint32_t)(((wm + (lane & 15)) * LDSP + kk + ((lane >> 4) << 3)) * 2);
            #pragma unroll
            for (int mi = 0; mi < 4; ++mi) {
                ldsm_x4(Ahf[mi][0], Ahf[mi][1], Ahf[mi][2], Ahf[mi][3],
                        sb + OFF_AH + abase + (uint32_t)(mi * 16 * ROWB));
                ldsm_x4(Alf[mi][0], Alf[mi][1], Alf[mi][2], Alf[mi][3],
                        sb + OFF_AL + abase + (uint32_t)(mi * 16 * ROWB));
            }
            const uint32_t bbase =
                (uint32_t)(((wn + ((lane >> 4) << 3) + (lane & 7)) * LDSP +
                            kk + (((lane >> 3) & 1) << 3)) * 2);
            #pragma unroll
            for (int nt = 0; nt < 4; ++nt) {
                ldsm_x4(Bhf[2 * nt][0], Bhf[2 * nt][1],
                        Bhf[2 * nt + 1][0], Bhf[2 * nt + 1][1],
                        sb + OFF_BH + bbase + (uint32_t)(nt * 16 * ROWB));
                if (NPASS == 3)
                    ldsm_x4(Blf[2 * nt][0], Blf[2 * nt][1],
                            Blf[2 * nt + 1][0], Blf[2 * nt + 1][1],
                            sb + OFF_BL + bbase + (uint32_t)(nt * 16 * ROWB));
            }

            #pragma unroll
            for (int mi = 0; mi < 4; ++mi)
                #pragma unroll
                for (int ni = 0; ni < 8; ++ni)
                    mma_f16(acc[mi][ni][0], acc[mi][ni][1], acc[mi][ni][2], acc[mi][ni][3],
                            Ahf[mi][0], Ahf[mi][1], Ahf[mi][2], Ahf[mi][3],
                            Bhf[ni][0], Bhf[ni][1]);
            if (NPASS == 3) {
                #pragma unroll
                for (int mi = 0; mi < 4; ++mi)
                    #pragma unroll
                    for (int ni = 0; ni < 8; ++ni)
                        mma_f16(acc[mi][ni][0], acc[mi][ni][1], acc[mi][ni][2], acc[mi][ni][3],
                                Ahf[mi][0], Ahf[mi][1], Ahf[mi][2], Ahf[mi][3],
                                Blf[ni][0], Blf[ni][1]);
            }
            #pragma unroll
            for (int mi = 0; mi < 4; ++mi)
                #pragma unroll
                for (int ni = 0; ni < 8; ++ni)
                    mma_f16(acc[mi][ni][0], acc[mi][ni][1], acc[mi][ni][2], acc[mi][ni][3],
                            Alf[mi][0], Alf[mi][1], Alf[mi][2], Alf[mi][3],
                            Bhf[ni][0], Bhf[ni][1]);
        }
        __syncthreads();
    }

    // ---- epilogue ----
    if (SPLIT_OUT) {
        f16* Ch = (f16*)Cp0 + (long long)blockIdx.z * sC;
        f16* Cl = (f16*)Cp1 + (long long)blockIdx.z * sC;
        #pragma unroll
        for (int mi = 0; mi < 4; ++mi) {
            #pragma unroll
            for (int ni = 0; ni < 8; ++ni) {
                int r = m0 + wm + mi * 16 + (lane >> 2);
                int c = n0 + wn + ni * 8 + (lane & 3) * 2;
                #pragma unroll
                for (int half = 0; half < 2; ++half) {
                    float a0 = acc[mi][ni][2 * half], a1 = acc[mi][ni][2 * half + 1];
                    f16 h0 = __float2half(a0), h1 = __float2half(a1);
                    size_t off = (size_t)(r + half * 8) * ldc + c;
                    *(f162*)&Ch[off] = __halves2half2(h0, h1);
                    *(f162*)&Cl[off] = __halves2half2(
                        __float2half(a0 - __half2float(h0)),
                        __float2half(a1 - __half2float(h1)));
                }
            }
        }
    } else {
        float* C = (float*)Cp0 + (long long)blockIdx.z * sC;
        #pragma unroll
        for (int mi = 0; mi < 4; ++mi) {
            #pragma unroll
            for (int ni = 0; ni < 8; ++ni) {
                int r = m0 + wm + mi * 16 + (lane >> 2);
                int c = n0 + wn + ni * 8 + (lane & 3) * 2;
                *(float2*)&C[(size_t)r * ldc + c] =
                    make_float2(acc[mi][ni][0], acc[mi][ni][1]);
                *(float2*)&C[(size_t)(r + 8) * ldc + c] =
                    make_float2(acc[mi][ni][2], acc[mi][ni][3]);
            }
        }
    }
}

// ---------------- masked softmax on hi/lo S (causal-bounded) ----------------
__global__ __launch_bounds__(256)
void softmax2(f16* __restrict__ Sh, f16* __restrict__ Sl)
{
    const int t = blockIdx.x;
    const int h = blockIdx.y;
    f16* rowh = Sh + ((size_t)h * TT + t) * TT;
    f16* rowl = Sl + ((size_t)h * TT + t) * TT;

    const float inv = 0.044194173824159216f; // 1/sqrt(512)
    const int tid = threadIdx.x;
    const int bound = ((t >> 7) + 1) << 7;

    __shared__ float red[256];

    float vals[8];
    float lmax = -INFINITY;
    #pragma unroll
    for (int i = 0; i < 8; ++i) {
        int s = tid + i * 256;
        if (s >= bound) break;
        float v = -INFINITY;
        if (s <= t) {
            v = (__half2float(rowh[s]) + __half2float(rowl[s])) * inv;
            if (t - s < RA_WIN) v *= 1.5f;
            lmax = fmaxf(lmax, v);
        }
        vals[i] = v;
    }
    red[tid] = lmax;
    __syncthreads();
    #pragma unroll
    for (int o = 128; o > 0; o >>= 1) {
        if (tid < o) red[tid] = fmaxf(red[tid], red[tid + o]);
        __syncthreads();
    }
    const float m = red[0];
    __syncthreads();

    float lsum = 0.f;
    #pragma unroll
    for (int i = 0; i < 8; ++i) {
        int s = tid + i * 256;
        if (s >= bound) break;
        float e = 0.f;
        if (s <= t) { e = __expf(vals[i] - m); lsum += e; }
        vals[i] = e;
    }
    red[tid] = lsum;
    __syncthreads();
    #pragma unroll
    for (int o = 128; o > 0; o >>= 1) {
        if (tid < o) red[tid] += red[tid + o];
        __syncthreads();
    }
    const float inv_sum = 1.0f / red[0];

    #pragma unroll
    for (int i = 0; i < 8; ++i) {
        int s = tid + i * 256;
        if (s >= bound) break;
        float p = vals[i] * inv_sum;
        f16 ph = __float2half(p);
        rowh[s] = ph;
        rowl[s] = __float2half(p - __half2float(ph));
    }
}

// ---------------- launch ----------------
extern "C" void kernel_launch(void* const* d_in, const int* in_sizes, int n_in,
                              void* d_out, int out_size)
{
    const float* hidden = (const float*)d_in[0]; // [T, E]
    const float* w_q    = (const float*)d_in[1]; // [E, E]
    const float* w_kd   = (const float*)d_in[2]; // [L, E]
    const float* w_vd   = (const float*)d_in[3]; // [L, E]
    const float* q2l    = (const float*)d_in[4]; // [H, D, L]
    const float* v_up   = (const float*)d_in[5]; // [H, L, D]
    const float* w_out  = (const float*)d_in[6]; // [E, E]
    float* out = (float*)d_out;                  // [T, E]

    f16 *hidh, *hidl, *wqh, *wql, *wkdh, *wkdl, *wvdh, *wvdl, *wouth, *woutl;
    f16 *q2lTh, *q2lTl, *vupTh, *vupTl;
    f16 *Qh, *Ql, *latkh, *latkl, *latvh, *latvl, *qlath, *qlatl;
    f16 *Vh, *Vl, *VTh, *VTl, *Sh, *Sl, *ctxh, *ctxl;
    cudaGetSymbolAddress((void**)&hidh, g_hidh);   cudaGetSymbolAddress((void**)&hidl, g_hidl);
    cudaGetSymbolAddress((void**)&wqh, g_wqh);     cudaGetSymbolAddress((void**)&wql, g_wql);
    cudaGetSymbolAddress((void**)&wkdh, g_wkdh);   cudaGetSymbolAddress((void**)&wkdl, g_wkdl);
    cudaGetSymbolAddress((void**)&wvdh, g_wvdh);   cudaGetSymbolAddress((void**)&wvdl, g_wvdl);
    cudaGetSymbolAddress((void**)&wouth, g_wouth); cudaGetSymbolAddress((void**)&woutl, g_woutl);
    cudaGetSymbolAddress((void**)&q2lTh, g_q2lTh); cudaGetSymbolAddress((void**)&q2lTl, g_q2lTl);
    cudaGetSymbolAddress((void**)&vupTh, g_vupTh); cudaGetSymbolAddress((void**)&vupTl, g_vupTl);
    cudaGetSymbolAddress((void**)&Qh, g_Qh);       cudaGetSymbolAddress((void**)&Ql, g_Ql);
    cudaGetSymbolAddress((void**)&latkh, g_latkh); cudaGetSymbolAddress((void**)&latkl, g_latkl);
    cudaGetSymbolAddress((void**)&latvh, g_latvh); cudaGetSymbolAddress((void**)&latvl, g_latvl);
    cudaGetSymbolAddress((void**)&qlath, g_qlath); cudaGetSymbolAddress((void**)&qlatl, g_qlatl);
    cudaGetSymbolAddress((void**)&Vh, g_Vh);       cudaGetSymbolAddress((void**)&Vl, g_Vl);
    cudaGetSymbolAddress((void**)&VTh, g_VTh);     cudaGetSymbolAddress((void**)&VTl, g_VTl);
    cudaGetSymbolAddress((void**)&Sh, g_Sh);       cudaGetSymbolAddress((void**)&Sl, g_Sl);
    cudaGetSymbolAddress((void**)&ctxh, g_ctxh);   cudaGetSymbolAddress((void**)&ctxl, g_ctxl);

    cudaFuncSetAttribute(gemm_ss<true, 3>,
                         cudaFuncAttributeMaxDynamicSharedMemorySize, GEMM_SMEM);
    cudaFuncSetAttribute(gemm_ss<true, 2>,
                         cudaFuncAttributeMaxDynamicSharedMemorySize, GEMM_SMEM);
    cudaFuncSetAttribute(gemm_ss<false, 2>,
                         cudaFuncAttributeMaxDynamicSharedMemorySize, GEMM_SMEM);

    // ---- conversions ----
    split_k<<<(TT * EE / 4 + 255) / 256, 256>>>(hidden, hidh, hidl, TT * EE / 4);
    split_k<<<(EE * EE / 4 + 255) / 256, 256>>>(w_q, wqh, wql, EE * EE / 4);
    split_k<<<(LL * EE / 4 + 255) / 256, 256>>>(w_kd, wkdh, wkdl, LL * EE / 4);
    split_k<<<(LL * EE / 4 + 255) / 256, 256>>>(w_vd, wvdh, wvdl, LL * EE / 4);
    split_k<<<(EE * EE / 4 + 255) / 256, 256>>>(w_out, wouth, woutl, EE * EE / 4);
    transposeSplit<<<dim3(LL / 32, DD / 32, HH), dim3(32, 8)>>>(q2l, q2lTh, q2lTl, DD, LL);
    transposeSplit<<<dim3(DD / 32, LL / 32, HH), dim3(32, 8)>>>(v_up, vupTh, vupTl, LL, DD);

    dim3 blk(128);
    const size_t sm = GEMM_SMEM;

    // 1) Q = hidden @ w_q^T  [2048,2048,2048]  (3-pass)
    gemm_ss<true, 3><<<dim3(EE / 128, TT / 128, 1), blk, sm>>>(
        hidh, hidl, EE, 0, wqh, wql, EE, 0, Qh, Ql, EE, 0, EE, 0);

    // 2) latent_k = hidden @ w_k_down^T  [2048,512,2048]  (3-pass)
    gemm_ss<true, 3><<<dim3(LL / 128, TT / 128, 1), blk, sm>>>(
        hidh, hidl, EE, 0, wkdh, wkdl, EE, 0, latkh, latkl, LL, 0, EE, 0);

    // 3) latent_v = hidden @ w_v_down^T  (3-pass)
    gemm_ss<true, 3><<<dim3(LL / 128, TT / 128, 1), blk, sm>>>(
        hidh, hidl, EE, 0, wvdh, wvdl, EE, 0, latvh, latvl, LL, 0, EE, 0);

    // 4) q_latent[h] = Q[:,hD:] @ q2lT[h]^T  [2048,512,128]  (3-pass)
    gemm_ss<true, 3><<<dim3(LL / 128, TT / 128, HH), blk, sm>>>(
        Qh, Ql, EE, DD, q2lTh, q2lTl, DD, (long long)LL * DD,
        qlath, qlatl, LL, (long long)TT * LL, DD, 0);

    // 5) V[:,h] = latent_v @ vupT[h]^T  [2048,128,512]  (2-pass: vup rounded)
    gemm_ss<true, 2><<<dim3(DD / 128, TT / 128, HH), blk, sm>>>(
        latvh, latvl, LL, 0, vupTh, nullptr, LL, (long long)DD * LL,
        Vh, Vl, EE, DD, LL, 0);

    // 6) S[h] = q_latent[h] @ latent_k^T  [2048,2048,512]
    //    causal tile skip + 2-pass (latent_k rounded)
    gemm_ss<true, 2><<<dim3(TT / 128, TT / 128, HH), blk, sm>>>(
        qlath, qlatl, LL, (long long)TT * LL, latkh, nullptr, LL, 0,
        Sh, Sl, TT, (long long)TT * TT, LL, 1);

    // 7) V^T: [T][E] -> [E][T]
    transpose2<<<dim3(EE / 32, TT / 32), dim3(32, 8)>>>(Vh, Vl, VTh, VTl, TT, EE);

    // 8) masked softmax in-place on (Sh, Sl), causal-bounded
    softmax2<<<dim3(TT, HH), dim3(256)>>>(Sh, Sl);

    // 9) ctx[:,h] = attn[h] @ VT[h]^T  [2048,128,2048]
    //    K capped per row tile + 2-pass (V rounded)
    gemm_ss<true, 2><<<dim3(DD / 128, TT / 128, HH), blk, sm>>>(
        Sh, Sl, TT, (long long)TT * TT, VTh, nullptr, TT, (long long)DD * TT,
        ctxh, ctxl, EE, DD, TT, 2);

    // 10) out = ctx @ w_out^T  [2048,2048,2048]  (2-pass: w_out rounded, fp32 out)
    gemm_ss<false, 2><<<dim3(EE / 128, TT / 128, 1), blk, sm>>>(
        ctxh, ctxl, EE, 0, wouth, nullptr, EE, 0, out, nullptr, EE, 0, EE, 0);
}

// round 8
// speedup vs baseline: 7.8617x; 1.1755x over previous
#include <cuda_runtime.h>
#include <cuda_fp16.h>
#include <math.h>
#include <stdint.h>

// Problem dims (fixed by the reference)
#define TT 2048   // tokens
#define EE 2048   // embed
#define HH 16     // heads
#define LL 512    // latent
#define DD 128    // head dim
#define RA_WIN 64

typedef __half f16;
typedef __half2 f162;

// ---------------- scratch (allocation-free: device globals) ----------------
__device__ f16 g_hidh[TT * EE],  g_hidl[TT * EE];
__device__ f16 g_wqh[EE * EE];
__device__ f16 g_wkdh[LL * EE];
__device__ f16 g_wvdh[LL * EE];
__device__ f16 g_wouth[EE * EE];
__device__ f16 g_q2lTh[HH * LL * DD], g_q2lTl[HH * LL * DD]; // [H][L][D]
__device__ f16 g_vupTh[HH * DD * LL];                        // [H][D][L]
__device__ f16 g_Qh[TT * EE],   g_Ql[TT * EE];
__device__ f16 g_latkh[TT * LL];
__device__ f16 g_latvh[TT * LL], g_latvl[TT * LL];
__device__ f16 g_qlath[(size_t)HH * TT * LL], g_qlatl[(size_t)HH * TT * LL];
__device__ f16 g_Vh[TT * EE];                 // [T][H*D]
__device__ f16 g_VTh[EE * TT];                // [H*D][T]
__device__ f16 g_Sh[(size_t)HH * TT * TT], g_Sl[(size_t)HH * TT * TT];
__device__ f16 g_ctxh[TT * EE], g_ctxl[TT * EE];

// ---------------- helpers ----------------
__device__ __forceinline__ uint32_t smem_u32(const void* p) {
    uint32_t a;
    asm("{ .reg .u64 t; cvta.to.shared.u64 t, %1; cvt.u32.u64 %0, t; }"
        : "=r"(a) : "l"(p));
    return a;
}

__device__ __forceinline__ void cp16(uint32_t dst, const void* src) {
    asm volatile("cp.async.cg.shared.global [%0], [%1], 16;" :: "r"(dst), "l"(src));
}
__device__ __forceinline__ void cp_commit() {
    asm volatile("cp.async.commit_group;" ::: "memory");
}
template <int N>
__device__ __forceinline__ void cp_wait() {
    asm volatile("cp.async.wait_group %0;" :: "n"(N) : "memory");
}

__device__ __forceinline__ void ldsm_x4(uint32_t& r0, uint32_t& r1,
                                        uint32_t& r2, uint32_t& r3,
                                        uint32_t addr) {
    asm volatile("ldmatrix.sync.aligned.m8n8.x4.shared.b16 {%0,%1,%2,%3}, [%4];\n"
                 : "=r"(r0), "=r"(r1), "=r"(r2), "=r"(r3)
                 : "r"(addr));
}

__device__ __forceinline__ void mma_f16(float& c0, float& c1, float& c2, float& c3,
                                        uint32_t a0, uint32_t a1, uint32_t a2, uint32_t a3,
                                        uint32_t b0, uint32_t b1) {
    asm volatile("mma.sync.aligned.m16n8k16.row.col.f32.f16.f16.f32 "
                 "{%0,%1,%2,%3}, {%4,%5,%6,%7}, {%8,%9}, {%0,%1,%2,%3};\n"
                 : "+f"(c0), "+f"(c1), "+f"(c2), "+f"(c3)
                 : "r"(a0), "r"(a1), "r"(a2), "r"(a3), "r"(b0), "r"(b1));
}

// ---------------- conversion kernels ----------------
__global__ __launch_bounds__(256)
void split_k(const float* __restrict__ in, f16* __restrict__ h,
             f16* __restrict__ l, int n4)
{
    int i = blockIdx.x * blockDim.x + threadIdx.x;
    if (i >= n4) return;
    float4 v = ((const float4*)in)[i];
    f16 hx = __float2half(v.x), hy = __float2half(v.y);
    f16 hz = __float2half(v.z), hw = __float2half(v.w);
    ((f162*)h)[2 * i]     = __halves2half2(hx, hy);
    ((f162*)h)[2 * i + 1] = __halves2half2(hz, hw);
    ((f162*)l)[2 * i] = __halves2half2(
        __float2half(v.x - __half2float(hx)),
        __float2half(v.y - __half2float(hy)));
    ((f162*)l)[2 * i + 1] = __halves2half2(
        __float2half(v.z - __half2float(hz)),
        __float2half(v.w - __half2float(hw)));
}

__global__ __launch_bounds__(256)
void split_k1(const float* __restrict__ in, f16* __restrict__ h, int n4)
{
    int i = blockIdx.x * blockDim.x + threadIdx.x;
    if (i >= n4) return;
    float4 v = ((const float4*)in)[i];
    ((f162*)h)[2 * i]     = __halves2half2(__float2half(v.x), __float2half(v.y));
    ((f162*)h)[2 * i + 1] = __halves2half2(__float2half(v.z), __float2half(v.w));
}

// in [z][R][C] fp32 -> out [z][C][R] hi/lo f16 (tiled transpose)
__global__ __launch_bounds__(256)
void transposeSplit(const float* __restrict__ in, f16* __restrict__ outh,
                    f16* __restrict__ outl, int R, int C)
{
    __shared__ float t[32][33];
    const size_t zoff = (size_t)blockIdx.z * R * C;
    in += zoff; outh += zoff; outl += zoff;
    const int c0 = blockIdx.x * 32, r0 = blockIdx.y * 32;
    const int tx = threadIdx.x;
    for (int i = threadIdx.y; i < 32; i += 8)
        t[i][tx] = in[(size_t)(r0 + i) * C + c0 + tx];
    __syncthreads();
    for (int i = threadIdx.y; i < 32; i += 8) {
        float v = t[tx][i];
        f16 hh = __float2half(v);
        outh[(size_t)(c0 + i) * R + r0 + tx] = hh;
        outl[(size_t)(c0 + i) * R + r0 + tx] =
            __float2half(v - __half2float(hh));
    }
}

// in [z][R][C] fp32 -> out [z][C][R] f16 hi only
__global__ __launch_bounds__(256)
void transposeH(const float* __restrict__ in, f16* __restrict__ outh,
                int R, int C)
{
    __shared__ float t[32][33];
    const size_t zoff = (size_t)blockIdx.z * R * C;
    in += zoff; outh += zoff;
    const int c0 = blockIdx.x * 32, r0 = blockIdx.y * 32;
    const int tx = threadIdx.x;
    for (int i = threadIdx.y; i < 32; i += 8)
        t[i][tx] = in[(size_t)(r0 + i) * C + c0 + tx];
    __syncthreads();
    for (int i = threadIdx.y; i < 32; i += 8)
        outh[(size_t)(c0 + i) * R + r0 + tx] = __float2half(t[tx][i]);
}

// f16 single-plane transpose: in [R][C] -> out [C][R]
__global__ __launch_bounds__(256)
void transpose1(const f16* __restrict__ in, f16* __restrict__ out, int R, int C)
{
    __shared__ f16 t[32][33];
    const int c0 = blockIdx.x * 32, r0 = blockIdx.y * 32;
    const int tx = threadIdx.x;
    for (int i = threadIdx.y; i < 32; i += 8)
        t[i][tx] = in[(size_t)(r0 + i) * C + c0 + tx];
    __syncthreads();
    for (int i = threadIdx.y; i < 32; i += 8)
        out[(size_t)(c0 + i) * R + r0 + tx] = t[tx][i];
}

// ---------------- split-fp16 NT GEMM (cp.async pipelined) ----------------
// C[M,N] = (Ah+Al)[M,K] @ op(B)^T, fp32 acc.
// NPASS=2: B=Bh only; passes AhBh + AlBh; 3 tiles/stage, 3-stage pipeline.
// NPASS=3: B=(Bh+Bl); + AhBl;          4 tiles/stage, 2-stage pipeline.
// OMODE: 0 = fp32 C, 1 = hi/lo f16 C, 2 = hi-only f16 C.
// mode: 0 = plain, 1 = causal tile skip, 2 = K-cap at (blockIdx.y+1)*128.
#define LDSP 40                    // padded row in f16 elems (80B)
#define ROWB (LDSP * 2)            // 80
#define TILEB (128 * ROWB)         // 10240
#define OFF_AH 0
#define OFF_AL TILEB
#define OFF_BH (2 * TILEB)
#define OFF_BL (3 * TILEB)

template <int OMODE, int NPASS>
__global__ __launch_bounds__(128, 2)
void gemm2(const f16* __restrict__ Ah, const f16* __restrict__ Al,
           int lda, long long sA,
           const f16* __restrict__ Bh, const f16* __restrict__ Bl,
           int ldb, long long sB,
           void* __restrict__ Cp0, void* __restrict__ Cp1,
           int ldc, long long sC, int K, int mode)
{
    if (mode == 1 && blockIdx.x > blockIdx.y) return;

    constexpr int NTILES = (NPASS == 3) ? 4 : 3;
    constexpr int STAGES = (NPASS == 3) ? 2 : 3;
    constexpr int STAGEB = NTILES * TILEB;

    extern __shared__ char smem[];
    const uint32_t sbase = smem_u32(smem);
    const int tid = threadIdx.x;
    const int lane = tid & 31;
    const int wid = tid >> 5;
    const int wm = (wid >> 1) * 64;
    const int wn = (wid & 1) * 64;

    Ah += (long long)blockIdx.z * sA;
    Al += (long long)blockIdx.z * sA;
    Bh += (long long)blockIdx.z * sB;
    if (NPASS == 3) Bl += (long long)blockIdx.z * sB;
    const int m0 = blockIdx.y * 128;
    const int n0 = blockIdx.x * 128;

    const int row = tid >> 2;
    const int ch = tid & 3;

    auto issue = [&](int g) {
        const int k0 = g << 5;
        const uint32_t sb = sbase + (g % STAGES) * STAGEB;
        #pragma unroll
        for (int i = 0; i < 4; ++i) {
            int r = row + i * 32;
            uint32_t doff = (uint32_t)(r * ROWB + ch * 16);
            cp16(sb + OFF_AH + doff, Ah + (size_t)(m0 + r) * lda + k0 + ch * 8);
            cp16(sb + OFF_AL + doff, Al + (size_t)(m0 + r) * lda + k0 + ch * 8);
            cp16(sb + OFF_BH + doff, Bh + (size_t)(n0 + r) * ldb + k0 + ch * 8);
            if (NPASS == 3)
                cp16(sb + OFF_BL + doff, Bl + (size_t)(n0 + r) * ldb + k0 + ch * 8);
        }
        cp_commit();
    };

    float acc[4][8][4] = {};
    int nIter = K >> 5;
    if (mode == 2) {
        int kc = (int)(blockIdx.y + 1) << 7;
        if (kc < K) nIter = kc >> 5;
    }

    #pragma unroll
    for (int s = 0; s < STAGES - 1; ++s)
        if (s < nIter) issue(s);

    for (int it = 0; it < nIter; ++it) {
        if (STAGES == 2) {
            if (it + 1 < nIter) { issue(it + 1); cp_wait<1>(); }
            else cp_wait<0>();
        } else {
            if (it < nIter - 1) cp_wait<1>();
            else cp_wait<0>();
        }
        __syncthreads();

        const uint32_t sb = sbase + (it % STAGES) * STAGEB;
        #pragma unroll
        for (int kk = 0; kk < 32; kk += 16) {
            uint32_t Ahf[4][4], Alf[4][4], Bhf[8][2], Blf[8][2];

            const uint32_t abase =
                (uint32_t)(((wm + (lane & 15)) * LDSP + kk + ((lane >> 4) << 3)) * 2);
            #pragma unroll
            for (int mi = 0; mi < 4; ++mi) {
                ldsm_x4(Ahf[mi][0], Ahf[mi][1], Ahf[mi][2], Ahf[mi][3],
                        sb + OFF_AH + abase + (uint32_t)(mi * 16 * ROWB));
                ldsm_x4(Alf[mi][0], Alf[mi][1], Alf[mi][2], Alf[mi][3],
                        sb + OFF_AL + abase + (uint32_t)(mi * 16 * ROWB));
            }
            const uint32_t bbase =
                (uint32_t)(((wn + ((lane >> 4) << 3) + (lane & 7)) * LDSP +
                            kk + (((lane >> 3) & 1) << 3)) * 2);
            #pragma unroll
            for (int nt = 0; nt < 4; ++nt) {
                ldsm_x4(Bhf[2 * nt][0], Bhf[2 * nt][1],
                        Bhf[2 * nt + 1][0], Bhf[2 * nt + 1][1],
                        sb + OFF_BH + bbase + (uint32_t)(nt * 16 * ROWB));
                if (NPASS == 3)
                    ldsm_x4(Blf[2 * nt][0], Blf[2 * nt][1],
                            Blf[2 * nt + 1][0], Blf[2 * nt + 1][1],
                            sb + OFF_BL + bbase + (uint32_t)(nt * 16 * ROWB));
            }

            #pragma unroll
            for (int mi = 0; mi < 4; ++mi)
                #pragma unroll
                for (int ni = 0; ni < 8; ++ni)
                    mma_f16(acc[mi][ni][0], acc[mi][ni][1], acc[mi][ni][2], acc[mi][ni][3],
                            Ahf[mi][0], Ahf[mi][1], Ahf[mi][2], Ahf[mi][3],
                            Bhf[ni][0], Bhf[ni][1]);
            if (NPASS == 3) {
                #pragma unroll
                for (int mi = 0; mi < 4; ++mi)
                    #pragma unroll
                    for (int ni = 0; ni < 8; ++ni)
                        mma_f16(acc[mi][ni][0], acc[mi][ni][1], acc[mi][ni][2], acc[mi][ni][3],
                                Ahf[mi][0], Ahf[mi][1], Ahf[mi][2], Ahf[mi][3],
                                Blf[ni][0], Blf[ni][1]);
            }
            #pragma unroll
            for (int mi = 0; mi < 4; ++mi)
                #pragma unroll
                for (int ni = 0; ni < 8; ++ni)
                    mma_f16(acc[mi][ni][0], acc[mi][ni][1], acc[mi][ni][2], acc[mi][ni][3],
                            Alf[mi][0], Alf[mi][1], Alf[mi][2], Alf[mi][3],
                            Bhf[ni][0], Bhf[ni][1]);
        }
        if (STAGES == 2) __syncthreads();
        else if (it + 2 < nIter) issue(it + 2);
    }

    // ---- epilogue ----
    if (OMODE == 0) {
        float* C = (float*)Cp0 + (long long)blockIdx.z * sC;
        #pragma unroll
        for (int mi = 0; mi < 4; ++mi) {
            #pragma unroll
            for (int ni = 0; ni < 8; ++ni) {
                int r = m0 + wm + mi * 16 + (lane >> 2);
                int c = n0 + wn + ni * 8 + (lane & 3) * 2;
                *(float2*)&C[(size_t)r * ldc + c] =
                    make_float2(acc[mi][ni][0], acc[mi][ni][1]);
                *(float2*)&C[(size_t)(r + 8) * ldc + c] =
                    make_float2(acc[mi][ni][2], acc[mi][ni][3]);
            }
        }
    } else {
        f16* Ch = (f16*)Cp0 + (long long)blockIdx.z * sC;
        f16* Cl = (OMODE == 1) ? (f16*)Cp1 + (long long)blockIdx.z * sC : nullptr;
        #pragma unroll
        for (int mi = 0; mi < 4; ++mi) {
            #pragma unroll
            for (int ni = 0; ni < 8; ++ni) {
                int r = m0 + wm + mi * 16 + (lane >> 2);
                int c = n0 + wn + ni * 8 + (lane & 3) * 2;
                #pragma unroll
                for (int half = 0; half < 2; ++half) {
                    float a0 = acc[mi][ni][2 * half], a1 = acc[mi][ni][2 * half + 1];
                    f16 h0 = __float2half(a0), h1 = __float2half(a1);
                    size_t off = (size_t)(r + half * 8) * ldc + c;
                    *(f162*)&Ch[off] = __halves2half2(h0, h1);
                    if (OMODE == 1)
                        *(f162*)&Cl[off] = __halves2half2(
                            __float2half(a0 - __half2float(h0)),
                            __float2half(a1 - __half2float(h1)));
                }
            }
        }
    }
}

// ---------------- masked softmax on hi/lo S (causal-bounded, half2) --------
__global__ __launch_bounds__(256)
void softmax2(f16* __restrict__ Sh, f16* __restrict__ Sl)
{
    const int t = blockIdx.x;
    const int h = blockIdx.y;
    f162* rowh = (f162*)(Sh + ((size_t)h * TT + t) * TT);
    f162* rowl = (f162*)(Sl + ((size_t)h * TT + t) * TT);

    const float inv = 0.044194173824159216f; // 1/sqrt(512)
    const int tid = threadIdx.x;
    const int boundp = (((t >> 7) + 1) << 7) >> 1;  // pairs

    __shared__ float red[256];

    float vals[8];
    float lmax = -INFINITY;
    #pragma unroll
    for (int i = 0; i < 4; ++i) {
        int sp = tid + i * 256;
        if (sp >= boundp) break;
        int s = sp * 2;
        float2 vh = __half22float2(rowh[sp]);
        float2 vl = __half22float2(rowl[sp]);
        float v0 = -INFINITY, v1 = -INFINITY;
        if (s <= t) {
            v0 = (vh.x + vl.x) * inv;
            if (t - s < RA_WIN) v0 *= 1.5f;
            lmax = fmaxf(lmax, v0);
        }
        if (s + 1 <= t) {
            v1 = (vh.y + vl.y) * inv;
            if (t - (s + 1) < RA_WIN) v1 *= 1.5f;
            lmax = fmaxf(lmax, v1);
        }
        vals[2 * i] = v0;
        vals[2 * i + 1] = v1;
    }
    red[tid] = lmax;
    __syncthreads();
    #pragma unroll
    for (int o = 128; o > 0; o >>= 1) {
        if (tid < o) red[tid] = fmaxf(red[tid], red[tid + o]);
        __syncthreads();
    }
    const float m = red[0];
    __syncthreads();

    float lsum = 0.f;
    #pragma unroll
    for (int i = 0; i < 4; ++i) {
        int sp = tid + i * 256;
        if (sp >= boundp) break;
        int s = sp * 2;
        float e0 = 0.f, e1 = 0.f;
        if (s <= t)     { e0 = __expf(vals[2 * i] - m);     lsum += e0; }
        if (s + 1 <= t) { e1 = __expf(vals[2 * i + 1] - m); lsum += e1; }
        vals[2 * i] = e0;
        vals[2 * i + 1] = e1;
    }
    red[tid] = lsum;
    __syncthreads();
    #pragma unroll
    for (int o = 128; o > 0; o >>= 1) {
        if (tid < o) red[tid] += red[tid + o];
        __syncthreads();
    }
    const float inv_sum = 1.0f / red[0];

    #pragma unroll
    for (int i = 0; i < 4; ++i) {
        int sp = tid + i * 256;
        if (sp >= boundp) break;
        float p0 = vals[2 * i] * inv_sum;
        float p1 = vals[2 * i + 1] * inv_sum;
        f16 h0 = __float2half(p0), h1 = __float2half(p1);
        rowh[sp] = __halves2half2(h0, h1);
        rowl[sp] = __halves2half2(
            __float2half(p0 - __half2float(h0)),
            __float2half(p1 - __half2float(h1)));
    }
}

// ---------------- launch ----------------
extern "C" void kernel_launch(void* const* d_in, const int* in_sizes, int n_in,
                              void* d_out, int out_size)
{
    const float* hidden = (const float*)d_in[0]; // [T, E]
    const float* w_q    = (const float*)d_in[1]; // [E, E]
    const float* w_kd   = (const float*)d_in[2]; // [L, E]
    const float* w_vd   = (const float*)d_in[3]; // [L, E]
    const float* q2l    = (const float*)d_in[4]; // [H, D, L]
    const float* v_up   = (const float*)d_in[5]; // [H, L, D]
    const float* w_out  = (const float*)d_in[6]; // [E, E]
    float* out = (float*)d_out;                  // [T, E]

    f16 *hidh, *hidl, *wqh, *wkdh, *wvdh, *wouth, *q2lTh, *q2lTl, *vupTh;
    f16 *Qh, *Ql, *latkh, *latvh, *latvl, *qlath, *qlatl;
    f16 *Vh, *VTh, *Sh, *Sl, *ctxh, *ctxl;
    cudaGetSymbolAddress((void**)&hidh, g_hidh);   cudaGetSymbolAddress((void**)&hidl, g_hidl);
    cudaGetSymbolAddress((void**)&wqh, g_wqh);
    cudaGetSymbolAddress((void**)&wkdh, g_wkdh);
    cudaGetSymbolAddress((void**)&wvdh, g_wvdh);
    cudaGetSymbolAddress((void**)&wouth, g_wouth);
    cudaGetSymbolAddress((void**)&q2lTh, g_q2lTh); cudaGetSymbolAddress((void**)&q2lTl, g_q2lTl);
    cudaGetSymbolAddress((void**)&vupTh, g_vupTh);
    cudaGetSymbolAddress((void**)&Qh, g_Qh);       cudaGetSymbolAddress((void**)&Ql, g_Ql);
    cudaGetSymbolAddress((void**)&latkh, g_latkh);
    cudaGetSymbolAddress((void**)&latvh, g_latvh); cudaGetSymbolAddress((void**)&latvl, g_latvl);
    cudaGetSymbolAddress((void**)&qlath, g_qlath); cudaGetSymbolAddress((void**)&qlatl, g_qlatl);
    cudaGetSymbolAddress((void**)&Vh, g_Vh);
    cudaGetSymbolAddress((void**)&VTh, g_VTh);
    cudaGetSymbolAddress((void**)&Sh, g_Sh);       cudaGetSymbolAddress((void**)&Sl, g_Sl);
    cudaGetSymbolAddress((void**)&ctxh, g_ctxh);   cudaGetSymbolAddress((void**)&ctxl, g_ctxl);

    const int SM2 = 3 * 3 * TILEB;   // 2-pass: 3 stages x 3 tiles = 92160
    const int SM3 = 2 * 4 * TILEB;   // 3-pass: 2 stages x 4 tiles = 81920
    cudaFuncSetAttribute(gemm2<1, 2>, cudaFuncAttributeMaxDynamicSharedMemorySize, SM2);
    cudaFuncSetAttribute(gemm2<2, 2>, cudaFuncAttributeMaxDynamicSharedMemorySize, SM2);
    cudaFuncSetAttribute(gemm2<0, 2>, cudaFuncAttributeMaxDynamicSharedMemorySize, SM2);
    cudaFuncSetAttribute(gemm2<1, 3>, cudaFuncAttributeMaxDynamicSharedMemorySize, SM3);

    // ---- conversions ----
    split_k<<<(TT * EE / 4 + 255) / 256, 256>>>(hidden, hidh, hidl, TT * EE / 4);
    split_k1<<<(EE * EE / 4 + 255) / 256, 256>>>(w_q, wqh, EE * EE / 4);
    split_k1<<<(LL * EE / 4 + 255) / 256, 256>>>(w_kd, wkdh, LL * EE / 4);
    split_k1<<<(LL * EE / 4 + 255) / 256, 256>>>(w_vd, wvdh, LL * EE / 4);
    split_k1<<<(EE * EE / 4 + 255) / 256, 256>>>(w_out, wouth, EE * EE / 4);
    transposeSplit<<<dim3(LL / 32, DD / 32, HH), dim3(32, 8)>>>(q2l, q2lTh, q2lTl, DD, LL);
    transposeH<<<dim3(DD / 32, LL / 32, HH), dim3(32, 8)>>>(v_up, vupTh, LL, DD);

    dim3 blk(128);

    // 1) Q = hidden @ w_q^T  [2048,2048,2048]  (2-pass, hi/lo out)
    gemm2<1, 2><<<dim3(EE / 128, TT / 128, 1), blk, SM2>>>(
        hidh, hidl, EE, 0, wqh, nullptr, EE, 0, Qh, Ql, EE, 0, EE, 0);

    // 2) latent_k = hidden @ w_k_down^T  [2048,512,2048]  (2-pass, hi-only out)
    gemm2<2, 2><<<dim3(LL / 128, TT / 128, 1), blk, SM2>>>(
        hidh, hidl, EE, 0, wkdh, nullptr, EE, 0, latkh, nullptr, LL, 0, EE, 0);

    // 3) latent_v = hidden @ w_v_down^T  (2-pass, hi/lo out)
    gemm2<1, 2><<<dim3(LL / 128, TT / 128, 1), blk, SM2>>>(
        hidh, hidl, EE, 0, wvdh, nullptr, EE, 0, latvh, latvl, LL, 0, EE, 0);

    // 4) q_latent[h] = Q[:,hD:] @ q2lT[h]^T  [2048,512,128]  (3-pass, hi/lo)
    gemm2<1, 3><<<dim3(LL / 128, TT / 128, HH), blk, SM3>>>(
        Qh, Ql, EE, DD, q2lTh, q2lTl, DD, (long long)LL * DD,
        qlath, qlatl, LL, (long long)TT * LL, DD, 0);

    // 5) V[:,h] = latent_v @ vupT[h]^T  [2048,128,512]  (2-pass, hi-only out)
    gemm2<2, 2><<<dim3(DD / 128, TT / 128, HH), blk, SM2>>>(
        latvh, latvl, LL, 0, vupTh, nullptr, LL, (long long)DD * LL,
        Vh, nullptr, EE, DD, LL, 0);

    // 6) S[h] = q_latent[h] @ latent_k^T  [2048,2048,512]
    //    causal tile skip, 2-pass, hi/lo out
    gemm2<1, 2><<<dim3(TT / 128, TT / 128, HH), blk, SM2>>>(
        qlath, qlatl, LL, (long long)TT * LL, latkh, nullptr, LL, 0,
        Sh, Sl, TT, (long long)TT * TT, LL, 1);

    // 7) V^T: [T][E] -> [E][T]  (hi only)
    transpose1<<<dim3(EE / 32, TT / 32), dim3(32, 8)>>>(Vh, VTh, TT, EE);

    // 8) masked softmax in-place on (Sh, Sl), causal-bounded
    softmax2<<<dim3(TT, HH), dim3(256)>>>(Sh, Sl);

    // 9) ctx[:,h] = attn[h] @ VT[h]^T  [2048,128,2048]
    //    K-cap per row tile, 2-pass, hi/lo out
    gemm2<1, 2><<<dim3(DD / 128, TT / 128, HH), blk, SM2>>>(
        Sh, Sl, TT, (long long)TT * TT, VTh, nullptr, TT, (long long)DD * TT,
        ctxh, ctxl, EE, DD, TT, 2);

    // 10) out = ctx @ w_out^T  [2048,2048,2048]  (2-pass, fp32 out)
    gemm2<0, 2><<<dim3(EE / 128, TT / 128, 1), blk, SM2>>>(
        ctxh, ctxl, EE, 0, wouth, nullptr, EE, 0, out, nullptr, EE, 0, EE, 0);
}

// round 10
// speedup vs baseline: 9.0748x; 1.1543x over previous
#include <cuda_runtime.h>
#include <cuda_fp16.h>
#include <math.h>
#include <stdint.h>

// Problem dims (fixed by the reference)
#define TT 2048   // tokens
#define EE 2048   // embed
#define HH 16     // heads
#define LL 512    // latent
#define DD 128    // head dim
#define RA_WIN 64

typedef __half f16;
typedef __half2 f162;

// ---------------- scratch (allocation-free: device globals) ----------------
__device__ f16 g_hidh[TT * EE],  g_hidl[TT * EE];
__device__ f16 g_wqh[EE * EE];
__device__ f16 g_wkdh[LL * EE];
__device__ f16 g_wvdh[LL * EE];
__device__ f16 g_wouth[EE * EE];
__device__ f16 g_q2lTh[HH * LL * DD];          // [H][L][D]
__device__ f16 g_vupTh[HH * DD * LL];          // [H][D][L]
__device__ f16 g_Qh[TT * EE],   g_Ql[TT * EE];
__device__ f16 g_latkh[TT * LL];
__device__ f16 g_latvh[TT * LL], g_latvl[TT * LL];
__device__ f16 g_qlath[(size_t)HH * TT * LL], g_qlatl[(size_t)HH * TT * LL];
__device__ f16 g_Vh[TT * EE];                  // [T][H*D]
__device__ f16 g_VTh[EE * TT];                 // [H*D][T]
__device__ f16 g_Sh[(size_t)HH * TT * TT], g_Sl[(size_t)HH * TT * TT];
__device__ f16 g_ctxh[TT * EE];

// ---------------- helpers ----------------
__device__ __forceinline__ uint32_t smem_u32(const void* p) {
    uint32_t a;
    asm("{ .reg .u64 t; cvta.to.shared.u64 t, %1; cvt.u32.u64 %0, t; }"
        : "=r"(a) : "l"(p));
    return a;
}

__device__ __forceinline__ void cp16(uint32_t dst, const void* src) {
    asm volatile("cp.async.cg.shared.global [%0], [%1], 16;" :: "r"(dst), "l"(src));
}
__device__ __forceinline__ void cp_commit() {
    asm volatile("cp.async.commit_group;" ::: "memory");
}
template <int N>
__device__ __forceinline__ void cp_wait() {
    asm volatile("cp.async.wait_group %0;" :: "n"(N) : "memory");
}

__device__ __forceinline__ void ldsm_x4(uint32_t& r0, uint32_t& r1,
                                        uint32_t& r2, uint32_t& r3,
                                        uint32_t addr) {
    asm volatile("ldmatrix.sync.aligned.m8n8.x4.shared.b16 {%0,%1,%2,%3}, [%4];\n"
                 : "=r"(r0), "=r"(r1), "=r"(r2), "=r"(r3)
                 : "r"(addr));
}

__device__ __forceinline__ void mma_f16(float& c0, float& c1, float& c2, float& c3,
                                        uint32_t a0, uint32_t a1, uint32_t a2, uint32_t a3,
                                        uint32_t b0, uint32_t b1) {
    asm volatile("mma.sync.aligned.m16n8k16.row.col.f32.f16.f16.f32 "
                 "{%0,%1,%2,%3}, {%4,%5,%6,%7}, {%8,%9}, {%0,%1,%2,%3};\n"
                 : "+f"(c0), "+f"(c1), "+f"(c2), "+f"(c3)
                 : "r"(a0), "r"(a1), "r"(a2), "r"(a3), "r"(b0), "r"(b1));
}

// ---------------- conversion kernels ----------------
__global__ __launch_bounds__(256)
void split_k(const float* __restrict__ in, f16* __restrict__ h,
             f16* __restrict__ l, int n4)
{
    int i = blockIdx.x * blockDim.x + threadIdx.x;
    if (i >= n4) return;
    float4 v = ((const float4*)in)[i];
    f16 hx = __float2half(v.x), hy = __float2half(v.y);
    f16 hz = __float2half(v.z), hw = __float2half(v.w);
    ((f162*)h)[2 * i]     = __halves2half2(hx, hy);
    ((f162*)h)[2 * i + 1] = __halves2half2(hz, hw);
    ((f162*)l)[2 * i] = __halves2half2(
        __float2half(v.x - __half2float(hx)),
        __float2half(v.y - __half2float(hy)));
    ((f162*)l)[2 * i + 1] = __halves2half2(
        __float2half(v.z - __half2float(hz)),
        __float2half(v.w - __half2float(hw)));
}

__global__ __launch_bounds__(256)
void split_k1(const float* __restrict__ in, f16* __restrict__ h, int n4)
{
    int i = blockIdx.x * blockDim.x + threadIdx.x;
    if (i >= n4) return;
    float4 v = ((const float4*)in)[i];
    ((f162*)h)[2 * i]     = __halves2half2(__float2half(v.x), __float2half(v.y));
    ((f162*)h)[2 * i + 1] = __halves2half2(__float2half(v.z), __float2half(v.w));
}

// in [z][R][C] fp32 -> out [z][C][R] f16 hi only
__global__ __launch_bounds__(256)
void transposeH(const float* __restrict__ in, f16* __restrict__ outh,
                int R, int C)
{
    __shared__ float t[32][33];
    const size_t zoff = (size_t)blockIdx.z * R * C;
    in += zoff; outh += zoff;
    const int c0 = blockIdx.x * 32, r0 = blockIdx.y * 32;
    const int tx = threadIdx.x;
    for (int i = threadIdx.y; i < 32; i += 8)
        t[i][tx] = in[(size_t)(r0 + i) * C + c0 + tx];
    __syncthreads();
    for (int i = threadIdx.y; i < 32; i += 8)
        outh[(size_t)(c0 + i) * R + r0 + tx] = __float2half(t[tx][i]);
}

// f16 single-plane transpose: in [R][C] -> out [C][R]
__global__ __launch_bounds__(256)
void transpose1(const f16* __restrict__ in, f16* __restrict__ out, int R, int C)
{
    __shared__ f16 t[32][33];
    const int c0 = blockIdx.x * 32, r0 = blockIdx.y * 32;
    const int tx = threadIdx.x;
    for (int i = threadIdx.y; i < 32; i += 8)
        t[i][tx] = in[(size_t)(r0 + i) * C + c0 + tx];
    __syncthreads();
    for (int i = threadIdx.y; i < 32; i += 8)
        out[(size_t)(c0 + i) * R + r0 + tx] = t[tx][i];
}

// ---------------- split-fp16 NT GEMM (cp.async pipelined) ----------------
// C[M,N] = A @ B^T, fp32 acc, 3-stage cp.async pipeline, CTA 128x128, BK=32.
// NPASS=2: A=(Ah+Al), B=Bh; passes AhBh + AlBh; 3 tiles/stage.
// NPASS=1: A=Ah, B=Bh; single pass; 2 tiles/stage.
// OMODE: 0 = fp32 C, 1 = hi/lo f16 C, 2 = hi-only f16 C.
// mode: 0 = plain, 1 = causal tile skip, 2 = K-cap at (blockIdx.y+1)*128.
#define LDSP 40                    // padded row in f16 elems (80B)
#define ROWB (LDSP * 2)            // 80
#define TILEB (128 * ROWB)         // 10240

template <int OMODE, int NPASS>
__global__ __launch_bounds__(128, 2)
void gemm2(const f16* __restrict__ Ah, const f16* __restrict__ Al,
           int lda, long long sA,
           const f16* __restrict__ Bh,
           int ldb, long long sB,
           void* __restrict__ Cp0, void* __restrict__ Cp1,
           int ldc, long long sC, int K, int mode)
{
    if (mode == 1 && blockIdx.x > blockIdx.y) return;

    constexpr int NTILES = (NPASS == 2) ? 3 : 2;
    constexpr int STAGES = 3;
    constexpr int STAGEB = NTILES * TILEB;
    constexpr uint32_t O_AH = 0;
    constexpr uint32_t O_AL = TILEB;                       // only if NPASS==2
    constexpr uint32_t O_BH = (NPASS == 2) ? 2 * TILEB : TILEB;

    extern __shared__ char smem[];
    const uint32_t sbase = smem_u32(smem);
    const int tid = threadIdx.x;
    const int lane = tid & 31;
    const int wid = tid >> 5;
    const int wm = (wid >> 1) * 64;
    const int wn = (wid & 1) * 64;

    Ah += (long long)blockIdx.z * sA;
    if (NPASS == 2) Al += (long long)blockIdx.z * sA;
    Bh += (long long)blockIdx.z * sB;
    const int m0 = blockIdx.y * 128;
    const int n0 = blockIdx.x * 128;

    const int row = tid >> 2;
    const int ch = tid & 3;

    auto issue = [&](int g) {
        const int k0 = g << 5;
        const uint32_t sb = sbase + (g % STAGES) * STAGEB;
        #pragma unroll
        for (int i = 0; i < 4; ++i) {
            int r = row + i * 32;
            uint32_t doff = (uint32_t)(r * ROWB + ch * 16);
            cp16(sb + O_AH + doff, Ah + (size_t)(m0 + r) * lda + k0 + ch * 8);
            if (NPASS == 2)
                cp16(sb + O_AL + doff, Al + (size_t)(m0 + r) * lda + k0 + ch * 8);
            cp16(sb + O_BH + doff, Bh + (size_t)(n0 + r) * ldb + k0 + ch * 8);
        }
        cp_commit();
    };

    float acc[4][8][4] = {};
    int nIter = K >> 5;
    if (mode == 2) {
        int kc = (int)(blockIdx.y + 1) << 7;
        if (kc < K) nIter = kc >> 5;
    }

    #pragma unroll
    for (int s = 0; s < STAGES - 1; ++s)
        if (s < nIter) issue(s);

    for (int it = 0; it < nIter; ++it) {
        if (it < nIter - 1) cp_wait<1>();
        else cp_wait<0>();
        __syncthreads();

        const uint32_t sb = sbase + (it % STAGES) * STAGEB;
        #pragma unroll
        for (int kk = 0; kk < 32; kk += 16) {
            uint32_t Ahf[4][4], Alf[4][4], Bhf[8][2];

            const uint32_t abase =
                (uint32_t)(((wm + (lane & 15)) * LDSP + kk + ((lane >> 4) << 3)) * 2);
            #pragma unroll
            for (int mi = 0; mi < 4; ++mi) {
                ldsm_x4(Ahf[mi][0], Ahf[mi][1], Ahf[mi][2], Ahf[mi][3],
                        sb + O_AH + abase + (uint32_t)(mi * 16 * ROWB));
                if (NPASS == 2)
                    ldsm_x4(Alf[mi][0], Alf[mi][1], Alf[mi][2], Alf[mi][3],
                            sb + O_AL + abase + (uint32_t)(mi * 16 * ROWB));
            }
            const uint32_t bbase =
                (uint32_t)(((wn + ((lane >> 4) << 3) + (lane & 7)) * LDSP +
                            kk + (((lane >> 3) & 1) << 3)) * 2);
            #pragma unroll
            for (int nt = 0; nt < 4; ++nt) {
                ldsm_x4(Bhf[2 * nt][0], Bhf[2 * nt][1],
                        Bhf[2 * nt + 1][0], Bhf[2 * nt + 1][1],
                        sb + O_BH + bbase + (uint32_t)(nt * 16 * ROWB));
            }

            #pragma unroll
            for (int mi = 0; mi < 4; ++mi)
                #pragma unroll
                for (int ni = 0; ni < 8; ++ni)
                    mma_f16(acc[mi][ni][0], acc[mi][ni][1], acc[mi][ni][2], acc[mi][ni][3],
                            Ahf[mi][0], Ahf[mi][1], Ahf[mi][2], Ahf[mi][3],
                            Bhf[ni][0], Bhf[ni][1]);
            if (NPASS == 2) {
                #pragma unroll
                for (int mi = 0; mi < 4; ++mi)
                    #pragma unroll
                    for (int ni = 0; ni < 8; ++ni)
                        mma_f16(acc[mi][ni][0], acc[mi][ni][1], acc[mi][ni][2], acc[mi][ni][3],
                                Alf[mi][0], Alf[mi][1], Alf[mi][2], Alf[mi][3],
                                Bhf[ni][0], Bhf[ni][1]);
            }
        }
        if (it + 2 < nIter) issue(it + 2);
    }

    // ---- epilogue ----
    if (OMODE == 0) {
        float* C = (float*)Cp0 + (long long)blockIdx.z * sC;
        #pragma unroll
        for (int mi = 0; mi < 4; ++mi) {
            #pragma unroll
            for (int ni = 0; ni < 8; ++ni) {
                int r = m0 + wm + mi * 16 + (lane >> 2);
                int c = n0 + wn + ni * 8 + (lane & 3) * 2;
                *(float2*)&C[(size_t)r * ldc + c] =
                    make_float2(acc[mi][ni][0], acc[mi][ni][1]);
                *(float2*)&C[(size_t)(r + 8) * ldc + c] =
                    make_float2(acc[mi][ni][2], acc[mi][ni][3]);
            }
        }
    } else {
        f16* Ch = (f16*)Cp0 + (long long)blockIdx.z * sC;
        f16* Cl = (OMODE == 1) ? (f16*)Cp1 + (long long)blockIdx.z * sC : nullptr;
        #pragma unroll
        for (int mi = 0; mi < 4; ++mi) {
            #pragma unroll
            for (int ni = 0; ni < 8; ++ni) {
                int r = m0 + wm + mi * 16 + (lane >> 2);
                int c = n0 + wn + ni * 8 + (lane & 3) * 2;
                #pragma unroll
                for (int half = 0; half < 2; ++half) {
                    float a0 = acc[mi][ni][2 * half], a1 = acc[mi][ni][2 * half + 1];
                    f16 h0 = __float2half(a0), h1 = __float2half(a1);
                    size_t off = (size_t)(r + half * 8) * ldc + c;
                    *(f162*)&Ch[off] = __halves2half2(h0, h1);
                    if (OMODE == 1)
                        *(f162*)&Cl[off] = __halves2half2(
                            __float2half(a0 - __half2float(h0)),
                            __float2half(a1 - __half2float(h1)));
                }
            }
        }
    }
}

// ---------------- masked softmax (reads hi/lo logits, writes hi probs) -----
__global__ __launch_bounds__(256)
void softmax2(f16* __restrict__ Sh, f16* __restrict__ Sl)
{
    const int t = blockIdx.x;
    const int h = blockIdx.y;
    f162* rowh = (f162*)(Sh + ((size_t)h * TT + t) * TT);
    f162* rowl = (f162*)(Sl + ((size_t)h * TT + t) * TT);

    const float inv = 0.044194173824159216f; // 1/sqrt(512)
    const int tid = threadIdx.x;
    const int boundp = (((t >> 7) + 1) << 7) >> 1;  // pairs

    __shared__ float red[256];

    float vals[8];
    float lmax = -INFINITY;
    #pragma unroll
    for (int i = 0; i < 4; ++i) {
        int sp = tid + i * 256;
        if (sp >= boundp) break;
        int s = sp * 2;
        float2 vh = __half22float2(rowh[sp]);
        float2 vl = __half22float2(rowl[sp]);
        float v0 = -INFINITY, v1 = -INFINITY;
        if (s <= t) {
            v0 = (vh.x + vl.x) * inv;
            if (t - s < RA_WIN) v0 *= 1.5f;
            lmax = fmaxf(lmax, v0);
        }
        if (s + 1 <= t) {
            v1 = (vh.y + vl.y) * inv;
            if (t - (s + 1) < RA_WIN) v1 *= 1.5f;
            lmax = fmaxf(lmax, v1);
        }
        vals[2 * i] = v0;
        vals[2 * i + 1] = v1;
    }
    red[tid] = lmax;
    __syncthreads();
    #pragma unroll
    for (int o = 128; o > 0; o >>= 1) {
        if (tid < o) red[tid] = fmaxf(red[tid], red[tid + o]);
        __syncthreads();
    }
    const float m = red[0];
    __syncthreads();

    float lsum = 0.f;
    #pragma unroll
    for (int i = 0; i < 4; ++i) {
        int sp = tid + i * 256;
        if (sp >= boundp) break;
        int s = sp * 2;
        float e0 = 0.f, e1 = 0.f;
        if (s <= t)     { e0 = __expf(vals[2 * i] - m);     lsum += e0; }
        if (s + 1 <= t) { e1 = __expf(vals[2 * i + 1] - m); lsum += e1; }
        vals[2 * i] = e0;
        vals[2 * i + 1] = e1;
    }
    red[tid] = lsum;
    __syncthreads();
    #pragma unroll
    for (int o = 128; o > 0; o >>= 1) {
        if (tid < o) red[tid] += red[tid + o];
        __syncthreads();
    }
    const float inv_sum = 1.0f / red[0];

    #pragma unroll
    for (int i = 0; i < 4; ++i) {
        int sp = tid + i * 256;
        if (sp >= boundp) break;
        rowh[sp] = __halves2half2(
            __float2half(vals[2 * i] * inv_sum),
            __float2half(vals[2 * i + 1] * inv_sum));
    }
}

// ---------------- launch ----------------
extern "C" void kernel_launch(void* const* d_in, const int* in_sizes, int n_in,
                              void* d_out, int out_size)
{
    const float* hidden = (const float*)d_in[0]; // [T, E]
    const float* w_q    = (const float*)d_in[1]; // [E, E]
    const float* w_kd   = (const float*)d_in[2]; // [L, E]
    const float* w_vd   = (const float*)d_in[3]; // [L, E]
    const float* q2l    = (const float*)d_in[4]; // [H, D, L]
    const float* v_up   = (const float*)d_in[5]; // [H, L, D]
    const float* w_out  = (const float*)d_in[6]; // [E, E]
    float* out = (float*)d_out;                  // [T, E]

    f16 *hidh, *hidl, *wqh, *wkdh, *wvdh, *wouth, *q2lTh, *vupTh;
    f16 *Qh, *Ql, *latkh, *latvh, *latvl, *qlath, *qlatl;
    f16 *Vh, *VTh, *Sh, *Sl, *ctxh;
    cudaGetSymbolAddress((void**)&hidh, g_hidh);   cudaGetSymbolAddress((void**)&hidl, g_hidl);
    cudaGetSymbolAddress((void**)&wqh, g_wqh);
    cudaGetSymbolAddress((void**)&wkdh, g_wkdh);
    cudaGetSymbolAddress((void**)&wvdh, g_wvdh);
    cudaGetSymbolAddress((void**)&wouth, g_wouth);
    cudaGetSymbolAddress((void**)&q2lTh, g_q2lTh);
    cudaGetSymbolAddress((void**)&vupTh, g_vupTh);
    cudaGetSymbolAddress((void**)&Qh, g_Qh);       cudaGetSymbolAddress((void**)&Ql, g_Ql);
    cudaGetSymbolAddress((void**)&latkh, g_latkh);
    cudaGetSymbolAddress((void**)&latvh, g_latvh); cudaGetSymbolAddress((void**)&latvl, g_latvl);
    cudaGetSymbolAddress((void**)&qlath, g_qlath); cudaGetSymbolAddress((void**)&qlatl, g_qlatl);
    cudaGetSymbolAddress((void**)&Vh, g_Vh);
    cudaGetSymbolAddress((void**)&VTh, g_VTh);
    cudaGetSymbolAddress((void**)&Sh, g_Sh);       cudaGetSymbolAddress((void**)&Sl, g_Sl);
    cudaGetSymbolAddress((void**)&ctxh, g_ctxh);

    const int SM2 = 3 * 3 * TILEB;   // 2-pass: 3 stages x 3 tiles = 92160
    const int SM1 = 3 * 2 * TILEB;   // 1-pass: 3 stages x 2 tiles = 61440
    cudaFuncSetAttribute(gemm2<1, 2>, cudaFuncAttributeMaxDynamicSharedMemorySize, SM2);
    cudaFuncSetAttribute(gemm2<2, 2>, cudaFuncAttributeMaxDynamicSharedMemorySize, SM2);
    cudaFuncSetAttribute(gemm2<2, 1>, cudaFuncAttributeMaxDynamicSharedMemorySize, SM1);
    cudaFuncSetAttribute(gemm2<0, 1>, cudaFuncAttributeMaxDynamicSharedMemorySize, SM1);

    // ---- conversions ----
    split_k<<<(TT * EE / 4 + 255) / 256, 256>>>(hidden, hidh, hidl, TT * EE / 4);
    split_k1<<<(EE * EE / 4 + 255) / 256, 256>>>(w_q, wqh, EE * EE / 4);
    split_k1<<<(LL * EE / 4 + 255) / 256, 256>>>(w_kd, wkdh, LL * EE / 4);
    split_k1<<<(LL * EE / 4 + 255) / 256, 256>>>(w_vd, wvdh, LL * EE / 4);
    split_k1<<<(EE * EE / 4 + 255) / 256, 256>>>(w_out, wouth, EE * EE / 4);
    transposeH<<<dim3(LL / 32, DD / 32, HH), dim3(32, 8)>>>(q2l, q2lTh, DD, LL);
    transposeH<<<dim3(DD / 32, LL / 32, HH), dim3(32, 8)>>>(v_up, vupTh, LL, DD);

    dim3 blk(128);

    // 1) Q = hidden @ w_q^T  [2048,2048,2048]  (2-pass, hi/lo out)
    gemm2<1, 2><<<dim3(EE / 128, TT / 128, 1), blk, SM2>>>(
        hidh, hidl, EE, 0, wqh, EE, 0, Qh, Ql, EE, 0, EE, 0);

    // 2) latent_k = hidden @ w_k_down^T  [2048,512,2048]  (2-pass, hi-only out)
    gemm2<2, 2><<<dim3(LL / 128, TT / 128, 1), blk, SM2>>>(
        hidh, hidl, EE, 0, wkdh, EE, 0, latkh, nullptr, LL, 0, EE, 0);

    // 3) latent_v = hidden @ w_v_down^T  (2-pass, hi/lo out)
    gemm2<1, 2><<<dim3(LL / 128, TT / 128, 1), blk, SM2>>>(
        hidh, hidl, EE, 0, wvdh, EE, 0, latvh, latvl, LL, 0, EE, 0);

    // 4) q_latent[h] = Q[:,hD:] @ q2lT[h]^T  [2048,512,128]  (2-pass, hi/lo)
    gemm2<1, 2><<<dim3(LL / 128, TT / 128, HH), blk, SM2>>>(
        Qh, Ql, EE, DD, q2lTh, DD, (long long)LL * DD,
        qlath, qlatl, LL, (long long)TT * LL, DD, 0);

    // 5) V[:,h] = latent_v @ vupT[h]^T  [2048,128,512]  (2-pass, hi-only out)
    gemm2<2, 2><<<dim3(DD / 128, TT / 128, HH), blk, SM2>>>(
        latvh, latvl, LL, 0, vupTh, LL, (long long)DD * LL,
        Vh, nullptr, EE, DD, LL, 0);

    // 6) S[h] = q_latent[h] @ latent_k^T  [2048,2048,512]
    //    causal tile skip, 2-pass, hi/lo logits out
    gemm2<1, 2><<<dim3(TT / 128, TT / 128, HH), blk, SM2>>>(
        qlath, qlatl, LL, (long long)TT * LL, latkh, LL, 0,
        Sh, Sl, TT, (long long)TT * TT, LL, 1);

    // 7) V^T: [T][E] -> [E][T]  (hi only)
    transpose1<<<dim3(EE / 32, TT / 32), dim3(32, 8)>>>(Vh, VTh, TT, EE);

    // 8) masked softmax: read hi/lo logits, write hi probs, causal-bounded
    softmax2<<<dim3(TT, HH), dim3(256)>>>(Sh, Sl);

    // 9) ctx[:,h] = attn[h] @ VT[h]^T  [2048,128,2048]
    //    K-cap per row tile, 1-pass, hi-only ctx out
    gemm2<2, 1><<<dim3(DD / 128, TT / 128, HH), blk, SM1>>>(
        Sh, nullptr, TT, (long long)TT * TT, VTh, TT, (long long)DD * TT,
        ctxh, nullptr, EE, DD, TT, 2);

    // 10) out = ctx @ w_out^T  [2048,2048,2048]  (1-pass, fp32 out)
    gemm2<0, 1><<<dim3(EE / 128, TT / 128, 1), blk, SM1>>>(
        ctxh, nullptr, EE, 0, wouth, EE, 0, out, nullptr, EE, 0, EE, 0);
}